// round 4
// baseline (speedup 1.0000x reference)
#include <cuda_runtime.h>

#define B_    64
#define S_    512
#define H_    128
#define NH_   4
#define NHH_  512
#define QSCALE 0.08838834764831845f   /* 1/sqrt(128) */
#define NEG_INF_ -1e9f

// ---------------- scratch (allocation-free: __device__ globals) --------------
__device__ float g_Q[(size_t)B_ * NH_ * S_ * H_];   // (b,h,s,d), tf32-rounded, pre-scaled
__device__ float g_K[(size_t)B_ * NH_ * S_ * H_];   // (b,h,s,d), tf32-rounded
__device__ float g_V[(size_t)B_ * NH_ * S_ * H_];   // (b,h,s,d), tf32-rounded
__device__ float g_ctx[(size_t)B_ * S_ * NHH_];     // (b,s, h*H+d), fp32

// ---------------- tf32 helpers ----------------------------------------------
__device__ __forceinline__ float tf32r(float x) {   // round-to-nearest tf32, as float bits
    unsigned u;
    asm("cvt.rna.tf32.f32 %0, %1;" : "=r"(u) : "f"(x));
    return __uint_as_float(u);
}

__device__ __forceinline__ void mma_tf32(float c[4],
                                         unsigned a0, unsigned a1, unsigned a2, unsigned a3,
                                         unsigned b0, unsigned b1) {
    asm volatile(
        "mma.sync.aligned.m16n8k8.row.col.f32.tf32.tf32.f32 "
        "{%0,%1,%2,%3}, {%4,%5,%6,%7}, {%8,%9}, {%0,%1,%2,%3};"
        : "+f"(c[0]), "+f"(c[1]), "+f"(c[2]), "+f"(c[3])
        : "r"(a0), "r"(a1), "r"(a2), "r"(a3), "r"(b0), "r"(b1));
}

// =============================================================================
// Kernel 1: fused QKV projection via tf32 MMA.
// X(32768x128) @ W(128x512) -> (b,h,s,d), rounded to tf32 (RN) on store.
// grid = (8 n-tiles, 512 m-tiles, 3 {Q,K,V}), 256 threads (8 warps: 4m x 2n),
// tile 64m x 64n x 128k (single k chunk).
// smem: Es 64x(pitch 132), Ws 128x(pitch 72) -> 70656 B dynamic.
// Fragment LDS bank patterns: A bank=(4*gid+8s+tig) distinct; B bank=(8*tig+8*nt+gid) distinct.
// =============================================================================
__global__ void __launch_bounds__(256, 2) qkv_kernel(
    const float* __restrict__ enc, const float* __restrict__ Wq,
    const float* __restrict__ Wk,  const float* __restrict__ Wv)
{
    extern __shared__ float sm[];
    float* Es = sm;             // 64 x 132
    float* Ws = sm + 64 * 132;  // 128 x 72

    const int tid  = threadIdx.x;
    const int lane = tid & 31, wid = tid >> 5;
    const int gid  = lane >> 2, tig = lane & 3;
    const int mw   = wid & 3,  nw  = wid >> 2;
    const int n0 = blockIdx.x * 64, m0 = blockIdx.y * 64, z = blockIdx.z;
    const float* W = (z == 0) ? Wq : (z == 1) ? Wk : Wv;

    // fill enc tile (64x128) and W tile (128x64), rounding inputs to tf32 RN
#pragma unroll
    for (int t = 0; t < 8; t++) {
        int idx = tid + t * 256;
        int r = idx >> 5, sl = idx & 31;
        float4 a = *reinterpret_cast<const float4*>(&enc[(size_t)(m0 + r) * H_ + sl * 4]);
        float* d = &Es[r * 132 + sl * 4];
        d[0] = tf32r(a.x); d[1] = tf32r(a.y); d[2] = tf32r(a.z); d[3] = tf32r(a.w);
    }
#pragma unroll
    for (int t = 0; t < 8; t++) {
        int idx = tid + t * 256;
        int r = idx >> 4, sl = idx & 15;
        float4 b = *reinterpret_cast<const float4*>(&W[(size_t)r * NHH_ + n0 + sl * 4]);
        float* d = &Ws[r * 72 + sl * 4];
        d[0] = tf32r(b.x); d[1] = tf32r(b.y); d[2] = tf32r(b.z); d[3] = tf32r(b.w);
    }
    __syncthreads();

    float c[4][4];
#pragma unroll
    for (int nt = 0; nt < 4; nt++)
#pragma unroll
        for (int j = 0; j < 4; j++) c[nt][j] = 0.0f;

    const unsigned* Eu = reinterpret_cast<const unsigned*>(Es);
    const unsigned* Wu = reinterpret_cast<const unsigned*>(Ws);
    const int r0 = mw * 16 + gid;

#pragma unroll
    for (int s = 0; s < 16; s++) {
        unsigned a0 = Eu[r0 * 132 + 8 * s + tig];
        unsigned a1 = Eu[(r0 + 8) * 132 + 8 * s + tig];
        unsigned a2 = Eu[r0 * 132 + 8 * s + tig + 4];
        unsigned a3 = Eu[(r0 + 8) * 132 + 8 * s + tig + 4];
#pragma unroll
        for (int nt = 0; nt < 4; nt++) {
            int nn = nw * 32 + nt * 8 + gid;
            unsigned b0 = Wu[(8 * s + tig) * 72 + nn];
            unsigned b1 = Wu[(8 * s + tig + 4) * 72 + nn];
            mma_tf32(c[nt], a0, a1, a2, a3, b0, b1);
        }
    }

    // epilogue: scale (Q only), round RN to tf32, scatter to (b,h,s,d)
    const float scl = (z == 0) ? QSCALE : 1.0f;
    float* dst = (z == 0) ? g_Q : (z == 1) ? g_K : g_V;
    const int m  = m0 + r0;
    const int bb = m >> 9, srow = m & 511;
    const int bb2 = (m + 8) >> 9, srow2 = (m + 8) & 511;
#pragma unroll
    for (int nt = 0; nt < 4; nt++) {
        int n = n0 + nw * 32 + nt * 8 + 2 * tig;
        int h = n >> 7, d = n & 127;
        float2 v0 = make_float2(tf32r(c[nt][0] * scl), tf32r(c[nt][1] * scl));
        float2 v1 = make_float2(tf32r(c[nt][2] * scl), tf32r(c[nt][3] * scl));
        *reinterpret_cast<float2*>(
            &dst[((size_t)(bb  * NH_ + h) * S_ + srow ) * H_ + d]) = v0;
        *reinterpret_cast<float2*>(
            &dst[((size_t)(bb2 * NH_ + h) * S_ + srow2) * H_ + d]) = v1;
    }
}

// =============================================================================
// Kernel 2: flash attention via tf32 MMA, masked, online softmax.
// grid = (8 q-tiles, NH, B), 256 threads (8 warps: 4m x 2n).
// q-tile 64, k-tile 64, D=128.
// smem (103424 B dynamic): Qs 64x132, Ks 64x132 (Ps 64x68 ALIASED on top of Ks
// — K tile is dead after QK^T each iter), Vs 64x136, rmax/rsum [2][64].
// 2 CTAs/SM (<=128 regs via launch_bounds).
// =============================================================================
__global__ void __launch_bounds__(256, 2) attn_kernel(const int* __restrict__ mask)
{
    extern __shared__ float sm[];
    float* Qs   = sm;                    // 64 x 132 = 8448
    float* Ks   = sm + 8448;             // 64 x 132 = 8448
    float* Ps   = Ks;                    // 64 x 68 (alias)
    float* Vs   = sm + 16896;            // 64 x 136 = 8704
    float* rmax = sm + 25600;            // [2][64]
    float* rsum = sm + 25728;            // [2][64]

    const int tid  = threadIdx.x;
    const int lane = tid & 31, wid = tid >> 5;
    const int gid  = lane >> 2, tig = lane & 3;
    const int mw   = wid & 3,  nw  = wid >> 2;
    const int q0 = blockIdx.x * 64;
    const int h  = blockIdx.y, bb = blockIdx.z;
    const size_t bh = (size_t)(bb * NH_ + h);
    const float* Qg = g_Q + bh * S_ * H_;
    const float* Kg = g_K + bh * S_ * H_;
    const float* Vg = g_V + bh * S_ * H_;

    // fill Q tile once
#pragma unroll
    for (int t = 0; t < 8; t++) {
        int idx = tid + t * 256;
        int r = idx >> 5, sl = idx & 31;
        *reinterpret_cast<float4*>(&Qs[r * 132 + sl * 4]) =
            *reinterpret_cast<const float4*>(&Qg[(size_t)(q0 + r) * H_ + sl * 4]);
    }

    float O[8][4];
#pragma unroll
    for (int nt = 0; nt < 8; nt++)
#pragma unroll
        for (int j = 0; j < 4; j++) O[nt][j] = 0.0f;
    float m0 = -1e30f, m1 = -1e30f, l0 = 0.0f, l1 = 0.0f;
    const int r0 = mw * 16 + gid;

    for (int kt = 0; kt < 8; kt++) {
        __syncthreads();                 // prev iter done with Ks(=Ps)/Vs; Qs ready
        const int k0 = kt * 64;
#pragma unroll
        for (int t = 0; t < 8; t++) {
            int idx = tid + t * 256;
            int r = idx >> 5, sl = idx & 31;
            *reinterpret_cast<float4*>(&Ks[r * 132 + sl * 4]) =
                *reinterpret_cast<const float4*>(&Kg[(size_t)(k0 + r) * H_ + sl * 4]);
            *reinterpret_cast<float4*>(&Vs[r * 136 + sl * 4]) =
                *reinterpret_cast<const float4*>(&Vg[(size_t)(k0 + r) * H_ + sl * 4]);
        }
        __syncthreads();

        // ---- S = Q K^T (Q pre-scaled) ----
        float c[4][4];
#pragma unroll
        for (int nt = 0; nt < 4; nt++)
#pragma unroll
            for (int j = 0; j < 4; j++) c[nt][j] = 0.0f;
        {
            const unsigned* Qu = reinterpret_cast<const unsigned*>(Qs);
            const unsigned* Ku = reinterpret_cast<const unsigned*>(Ks);
#pragma unroll
            for (int s = 0; s < 16; s++) {
                unsigned a0 = Qu[r0 * 132 + 8 * s + tig];
                unsigned a1 = Qu[(r0 + 8) * 132 + 8 * s + tig];
                unsigned a2 = Qu[r0 * 132 + 8 * s + tig + 4];
                unsigned a3 = Qu[(r0 + 8) * 132 + 8 * s + tig + 4];
#pragma unroll
                for (int nt = 0; nt < 4; nt++) {
                    int kn = nw * 32 + nt * 8 + gid;
                    unsigned b0 = Ku[kn * 132 + 8 * s + tig];
                    unsigned b1 = Ku[kn * 132 + 8 * s + tig + 4];
                    mma_tf32(c[nt], a0, a1, a2, a3, b0, b1);
                }
            }
        }

        // ---- mask + row max (thread -> quad -> cross-warp) ----
        float mx0 = -1e30f, mx1 = -1e30f;
#pragma unroll
        for (int nt = 0; nt < 4; nt++) {
            int kc = k0 + nw * 32 + nt * 8 + 2 * tig;
            int2 mk0 = *reinterpret_cast<const int2*>(
                &mask[((size_t)bb * S_ + (q0 + r0)) * S_ + kc]);
            int2 mk1 = *reinterpret_cast<const int2*>(
                &mask[((size_t)bb * S_ + (q0 + r0 + 8)) * S_ + kc]);
            if (mk0.x == 0) c[nt][0] = NEG_INF_;
            if (mk0.y == 0) c[nt][1] = NEG_INF_;
            if (mk1.x == 0) c[nt][2] = NEG_INF_;
            if (mk1.y == 0) c[nt][3] = NEG_INF_;
            mx0 = fmaxf(mx0, fmaxf(c[nt][0], c[nt][1]));
            mx1 = fmaxf(mx1, fmaxf(c[nt][2], c[nt][3]));
        }
        mx0 = fmaxf(mx0, __shfl_xor_sync(0xffffffffu, mx0, 1));
        mx0 = fmaxf(mx0, __shfl_xor_sync(0xffffffffu, mx0, 2));
        mx1 = fmaxf(mx1, __shfl_xor_sync(0xffffffffu, mx1, 1));
        mx1 = fmaxf(mx1, __shfl_xor_sync(0xffffffffu, mx1, 2));
        if (tig == 0) {
            rmax[nw * 64 + r0]     = mx0;
            rmax[nw * 64 + r0 + 8] = mx1;
        }
        __syncthreads();                 // rmax ready; Ks reads done (Ps writes safe)

        float nm0 = fmaxf(m0, fmaxf(rmax[r0],     rmax[64 + r0]));
        float nm1 = fmaxf(m1, fmaxf(rmax[r0 + 8], rmax[64 + r0 + 8]));
        float al0 = __expf(m0 - nm0), al1 = __expf(m1 - nm1);
        m0 = nm0; m1 = nm1;

        float s0 = 0.0f, s1 = 0.0f;
#pragma unroll
        for (int nt = 0; nt < 4; nt++) {
            float p0 = __expf(c[nt][0] - nm0);
            float p1 = __expf(c[nt][1] - nm0);
            float p2 = __expf(c[nt][2] - nm1);
            float p3 = __expf(c[nt][3] - nm1);
            s0 += p0 + p1; s1 += p2 + p3;
            int col = nw * 32 + nt * 8 + 2 * tig;
            *reinterpret_cast<float2*>(&Ps[r0 * 68 + col]) =
                make_float2(tf32r(p0), tf32r(p1));
            *reinterpret_cast<float2*>(&Ps[(r0 + 8) * 68 + col]) =
                make_float2(tf32r(p2), tf32r(p3));
        }
        s0 += __shfl_xor_sync(0xffffffffu, s0, 1);
        s0 += __shfl_xor_sync(0xffffffffu, s0, 2);
        s1 += __shfl_xor_sync(0xffffffffu, s1, 1);
        s1 += __shfl_xor_sync(0xffffffffu, s1, 2);
        if (tig == 0) {
            rsum[nw * 64 + r0]     = s0;
            rsum[nw * 64 + r0 + 8] = s1;
        }
        // rescale O while waiting
#pragma unroll
        for (int nt = 0; nt < 8; nt++) {
            O[nt][0] *= al0; O[nt][1] *= al0;
            O[nt][2] *= al1; O[nt][3] *= al1;
        }
        __syncthreads();                 // Ps + rsum visible

        l0 = l0 * al0 + rsum[r0]     + rsum[64 + r0];
        l1 = l1 * al1 + rsum[r0 + 8] + rsum[64 + r0 + 8];

        // ---- O += P @ V ----
        {
            const unsigned* Pu = reinterpret_cast<const unsigned*>(Ps);
            const unsigned* Vu = reinterpret_cast<const unsigned*>(Vs);
#pragma unroll
            for (int ks = 0; ks < 8; ks++) {
                unsigned a0 = Pu[r0 * 68 + 8 * ks + tig];
                unsigned a1 = Pu[(r0 + 8) * 68 + 8 * ks + tig];
                unsigned a2 = Pu[r0 * 68 + 8 * ks + tig + 4];
                unsigned a3 = Pu[(r0 + 8) * 68 + 8 * ks + tig + 4];
#pragma unroll
                for (int nt = 0; nt < 8; nt++) {
                    int d = nw * 64 + nt * 8 + gid;
                    unsigned b0 = Vu[(8 * ks + tig) * 136 + d];
                    unsigned b1 = Vu[(8 * ks + tig + 4) * 136 + d];
                    mma_tf32(O[nt], a0, a1, a2, a3, b0, b1);
                }
            }
        }
    }

    // ---- normalize + write ctx (b, s, h*H+d) ----
    float inv0 = 1.0f / l0, inv1 = 1.0f / l1;
#pragma unroll
    for (int nt = 0; nt < 8; nt++) {
        int d = nw * 64 + nt * 8 + 2 * tig;
        *reinterpret_cast<float2*>(
            &g_ctx[((size_t)bb * S_ + (q0 + r0)) * NHH_ + h * H_ + d]) =
            make_float2(O[nt][0] * inv0, O[nt][1] * inv0);
        *reinterpret_cast<float2*>(
            &g_ctx[((size_t)bb * S_ + (q0 + r0 + 8)) * NHH_ + h * H_ + d]) =
            make_float2(O[nt][2] * inv1, O[nt][3] * inv1);
    }
}

// ---------------- swizzled float4 tiles for the fp32 out kernel --------------
__device__ __forceinline__ float4 ld4sw(const float* b, int row, int slot, int nsl) {
    int ph = slot ^ (row & (nsl - 1));
    return *reinterpret_cast<const float4*>(b + ((row * nsl + ph) << 2));
}
__device__ __forceinline__ void st4sw(float* b, int row, int slot, int nsl, float4 v) {
    int ph = slot ^ (row & (nsl - 1));
    *reinterpret_cast<float4*>(b + ((row * nsl + ph) << 2)) = v;
}

// =============================================================================
// Kernel 3: out = ctx @ Wo + enc, then LayerNorm(last dim).  (fp32 FFMA)
// =============================================================================
__global__ void __launch_bounds__(256) out_kernel(
    const float* __restrict__ enc, const float* __restrict__ Wo,
    const float* __restrict__ gamma, const float* __restrict__ beta,
    float* __restrict__ out)
{
    __shared__ float As[64 * 32];    // 64 m-rows x 8 slots (k)
    __shared__ float Bs[32 * 128];   // 32 k-rows x 32 slots (n)
    const int tid = threadIdx.x, tx = tid & 15, ty = tid >> 4;
    const int m0 = blockIdx.x * 64;

    float acc[4][8];
#pragma unroll
    for (int i = 0; i < 4; i++)
#pragma unroll
        for (int j = 0; j < 8; j++) acc[i][j] = 0.0f;

    for (int kc = 0; kc < NHH_; kc += 32) {
        if (kc) __syncthreads();
#pragma unroll
        for (int t = 0; t < 2; t++) {
            int idx = tid + t * 256;
            int r = idx >> 3, sl = idx & 7;
            st4sw(As, r, sl, 8,
                  *reinterpret_cast<const float4*>(&g_ctx[(size_t)(m0 + r) * NHH_ + kc + sl * 4]));
        }
#pragma unroll
        for (int t = 0; t < 4; t++) {
            int idx = tid + t * 256;
            int r = idx >> 5, sl = idx & 31;
            st4sw(Bs, r, sl, 32,
                  *reinterpret_cast<const float4*>(&Wo[(size_t)(kc + r) * H_ + sl * 4]));
        }
        __syncthreads();
#pragma unroll
        for (int s = 0; s < 8; s++) {
            float4 av[4];
#pragma unroll
            for (int i = 0; i < 4; i++) av[i] = ld4sw(As, 4 * ty + i, s, 8);
#pragma unroll
            for (int t = 0; t < 4; t++) {
                int k = 4 * s + t;
                float4 b1 = ld4sw(Bs, k, tx, 32);
                float4 b2 = ld4sw(Bs, k, tx + 16, 32);
#pragma unroll
                for (int i = 0; i < 4; i++) {
                    float a = reinterpret_cast<const float*>(&av[i])[t];
                    acc[i][0] += a * b1.x; acc[i][1] += a * b1.y;
                    acc[i][2] += a * b1.z; acc[i][3] += a * b1.w;
                    acc[i][4] += a * b2.x; acc[i][5] += a * b2.y;
                    acc[i][6] += a * b2.z; acc[i][7] += a * b2.w;
                }
            }
        }
    }

    float4 g1  = *reinterpret_cast<const float4*>(&gamma[4 * tx]);
    float4 g2  = *reinterpret_cast<const float4*>(&gamma[64 + 4 * tx]);
    float4 be1 = *reinterpret_cast<const float4*>(&beta[4 * tx]);
    float4 be2 = *reinterpret_cast<const float4*>(&beta[64 + 4 * tx]);

#pragma unroll
    for (int i = 0; i < 4; i++) {
        int m = m0 + 4 * ty + i;
        float4 e1 = *reinterpret_cast<const float4*>(&enc[(size_t)m * H_ + 4 * tx]);
        float4 e2 = *reinterpret_cast<const float4*>(&enc[(size_t)m * H_ + 64 + 4 * tx]);
        float x[8];
        x[0] = acc[i][0] + e1.x; x[1] = acc[i][1] + e1.y;
        x[2] = acc[i][2] + e1.z; x[3] = acc[i][3] + e1.w;
        x[4] = acc[i][4] + e2.x; x[5] = acc[i][5] + e2.y;
        x[6] = acc[i][6] + e2.z; x[7] = acc[i][7] + e2.w;

        float sm_ = 0.0f, sq = 0.0f;
#pragma unroll
        for (int j = 0; j < 8; j++) { sm_ += x[j]; sq += x[j] * x[j]; }
#pragma unroll
        for (int o = 8; o > 0; o >>= 1) {
            sm_ += __shfl_xor_sync(0xffffffffu, sm_, o);
            sq  += __shfl_xor_sync(0xffffffffu, sq,  o);
        }
        float mean = sm_ * (1.0f / 128.0f);
        float var  = sq * (1.0f / 128.0f) - mean * mean;
        float rstd = rsqrtf(var + 1e-6f);

        float4 y1 = make_float4((x[0] - mean) * rstd * g1.x + be1.x,
                                (x[1] - mean) * rstd * g1.y + be1.y,
                                (x[2] - mean) * rstd * g1.z + be1.z,
                                (x[3] - mean) * rstd * g1.w + be1.w);
        float4 y2 = make_float4((x[4] - mean) * rstd * g2.x + be2.x,
                                (x[5] - mean) * rstd * g2.y + be2.y,
                                (x[6] - mean) * rstd * g2.z + be2.z,
                                (x[7] - mean) * rstd * g2.w + be2.w);
        *reinterpret_cast<float4*>(&out[(size_t)m * H_ + 4 * tx]) = y1;
        *reinterpret_cast<float4*>(&out[(size_t)m * H_ + 64 + 4 * tx]) = y2;
    }
}

// =============================================================================
extern "C" void kernel_launch(void* const* d_in, const int* in_sizes, int n_in,
                              void* d_out, int out_size)
{
    const float* enc   = (const float*)d_in[0];
    const int*   mask  = (const int*)  d_in[1];
    const float* Wq    = (const float*)d_in[2];
    const float* Wk    = (const float*)d_in[3];
    const float* Wv    = (const float*)d_in[4];
    const float* Wo    = (const float*)d_in[5];
    const float* gamma = (const float*)d_in[6];
    const float* beta  = (const float*)d_in[7];
    float* out = (float*)d_out;

    const int smem1 = (64 * 132 + 128 * 72) * (int)sizeof(float);   // 70656 B
    cudaFuncSetAttribute(qkv_kernel, cudaFuncAttributeMaxDynamicSharedMemorySize, smem1);
    dim3 g1(NHH_ / 64, (B_ * S_) / 64, 3);
    qkv_kernel<<<g1, 256, smem1>>>(enc, Wq, Wk, Wv);

    const int smem2 = (64 * 132 + 64 * 132 + 64 * 136 + 256) * (int)sizeof(float); // 103424 B
    cudaFuncSetAttribute(attn_kernel, cudaFuncAttributeMaxDynamicSharedMemorySize, smem2);
    dim3 g2(S_ / 64, NH_, B_);
    attn_kernel<<<g2, 256, smem2>>>(mask);

    out_kernel<<<(B_ * S_) / 64, 256>>>(enc, Wo, gamma, beta, out);
}

// round 7
// speedup vs baseline: 1.1307x; 1.1307x over previous
#include <cuda_runtime.h>

#define B_    64
#define S_    512
#define H_    128
#define NH_   4
#define NHH_  512
#define QSCALE 0.08838834764831845f   /* 1/sqrt(128) */
#define NEG_INF_ -1e9f

// ---------------- packed scratch (allocation-free __device__ globals) --------
// Pair packing along the MMA k-dim: element k lives in pair k2 = 4*(k>>3)+(k&3),
// component = (k>>2)&1, i.e. float2 = (T[k], T[k+4]).
__device__ float2 g_Qp [(size_t)B_ * NH_ * S_ * 64];    // [bh][s][k2_d]  (Q pre-scaled)
__device__ float2 g_Kp [(size_t)B_ * NH_ * S_ * 64];    // [bh][s][k2_d]
__device__ float2 g_Vtp[(size_t)B_ * NH_ * H_ * 256];   // [bh][d][k2_kv] (V transposed)
__device__ float2 g_ctxp[(size_t)B_ * S_ * 256];        // [tok][k2_nhh]
__device__ float2 g_Wp [3 * 512 * 64];                  // [mat][n][k2_k], tf32, Wq*QSCALE
__device__ float2 g_Wop[128 * 256];                     // [n][k2_k], tf32

// ---------------- tf32 helpers ----------------------------------------------
__device__ __forceinline__ float tf32r(float x) {
    unsigned u;
    asm("cvt.rna.tf32.f32 %0, %1;" : "=r"(u) : "f"(x));
    return __uint_as_float(u);
}
__device__ __forceinline__ unsigned fu(float x) { return __float_as_uint(x); }

__device__ __forceinline__ void mma_tf32(float c[4],
                                         unsigned a0, unsigned a1, unsigned a2, unsigned a3,
                                         unsigned b0, unsigned b1) {
    asm volatile(
        "mma.sync.aligned.m16n8k8.row.col.f32.tf32.tf32.f32 "
        "{%0,%1,%2,%3}, {%4,%5,%6,%7}, {%8,%9}, {%0,%1,%2,%3};"
        : "+f"(c[0]), "+f"(c[1]), "+f"(c[2]), "+f"(c[3])
        : "r"(a0), "r"(a1), "r"(a2), "r"(a3), "r"(b0), "r"(b1));
}

// =============================================================================
// Kernel 0: pack weights (tf32 RN, QSCALE folded into Wq).
// 3*512*64 + 128*256 = 131072 threads exactly.
// =============================================================================
__global__ void __launch_bounds__(256) prep_kernel(
    const float* __restrict__ Wq, const float* __restrict__ Wk,
    const float* __restrict__ Wv, const float* __restrict__ Wo)
{
    int idx = blockIdx.x * 256 + threadIdx.x;
    if (idx < 3 * 512 * 64) {
        int k2 = idx & 63, n = (idx >> 6) & 511, mat = idx >> 15;
        const float* W = (mat == 0) ? Wq : (mat == 1) ? Wk : Wv;
        int k = ((k2 >> 2) << 3) | (k2 & 3);
        float x = W[(size_t)k * NHH_ + n], y = W[(size_t)(k + 4) * NHH_ + n];
        if (mat == 0) { x *= QSCALE; y *= QSCALE; }
        g_Wp[idx] = make_float2(tf32r(x), tf32r(y));
    } else {
        int j = idx - 3 * 512 * 64;
        int k2 = j & 255, n = j >> 8;
        int k = ((k2 >> 2) << 3) | (k2 & 3);
        g_Wop[j] = make_float2(tf32r(Wo[(size_t)k * H_ + n]),
                               tf32r(Wo[(size_t)(k + 4) * H_ + n]));
    }
}

// =============================================================================
// Kernel 1: QKV projection, m-resident.  CTA = 64 tokens; loops 12 (mat,hq)
// chunks of 128 n-cols; enc read ONCE per CTA.  8 warps (2m x 4n), warp tile
// 32m x 32n, k=128.  smem: Ap 64x68 f2 + Ws 128x68 f2 = 104448 B.
// Epilogue packs Q/K by d (shfl_xor 2) and V transposed by kv (shfl_xor 16).
// =============================================================================
__global__ void __launch_bounds__(256, 2) qkv_kernel(const float* __restrict__ enc)
{
    extern __shared__ float sm[];
    float2* Ap = (float2*)sm;                   // 64 x 68 pairs
    float2* Ws = (float2*)(sm + 64 * 68 * 2);   // 128 x 68 pairs
    const int tid = threadIdx.x, lane = tid & 31, wid = tid >> 5;
    const int gid = lane >> 2, tig = lane & 3;
    const int mw = wid & 1, nw = wid >> 1;
    const int m0 = blockIdx.x * 64;
    const int r0 = mw * 32 + gid;

    // ---- pack enc tile (tf32 RN) into pair layout (element-wise) ----
#pragma unroll
    for (int t = 0; t < 8; t++) {
        int idx = tid + t * 256;
        int r = idx >> 5, sl = idx & 31;
        float4 a = *(const float4*)&enc[(size_t)(m0 + r) * H_ + sl * 4];
        int s2 = sl >> 1, hcomp = sl & 1;
        float* d = (float*)&Ap[r * 68 + 4 * s2];
        d[0 + hcomp] = tf32r(a.x); d[2 + hcomp] = tf32r(a.y);
        d[4 + hcomp] = tf32r(a.z); d[6 + hcomp] = tf32r(a.w);
    }

    for (int ch = 0; ch < 12; ch++) {
        const int mat = ch >> 2, hq = ch & 3;
        __syncthreads();
        // fill W chunk: 128 n-rows x 64 pairs (FIXED: full row coverage)
#pragma unroll
        for (int t = 0; t < 16; t++) {
            int idx = tid + t * 256;
            int r = idx >> 5, sl = idx & 31;
            float4 w = *(const float4*)&g_Wp[(((size_t)mat * 512 + hq * 128 + r) << 6) + sl * 2];
            *(float4*)&Ws[r * 68 + sl * 2] = w;
        }
        __syncthreads();

        float c[2][4][4];
#pragma unroll
        for (int mt = 0; mt < 2; mt++)
#pragma unroll
            for (int nt = 0; nt < 4; nt++)
#pragma unroll
                for (int j = 0; j < 4; j++) c[mt][nt][j] = 0.0f;

#pragma unroll
        for (int s = 0; s < 16; s++) {
            float2 a00 = Ap[(r0)      * 68 + 4 * s + tig];
            float2 a01 = Ap[(r0 + 8)  * 68 + 4 * s + tig];
            float2 a10 = Ap[(r0 + 16) * 68 + 4 * s + tig];
            float2 a11 = Ap[(r0 + 24) * 68 + 4 * s + tig];
#pragma unroll
            for (int nt = 0; nt < 4; nt++) {
                float2 b = Ws[(nw * 32 + nt * 8 + gid) * 68 + 4 * s + tig];
                mma_tf32(c[0][nt], fu(a00.x), fu(a01.x), fu(a00.y), fu(a01.y), fu(b.x), fu(b.y));
                mma_tf32(c[1][nt], fu(a10.x), fu(a11.x), fu(a10.y), fu(a11.y), fu(b.x), fu(b.y));
            }
        }

        if (mat < 2) {
            // ---- Q/K: pack by d via shfl_xor 2; tig<2 writes float4 (2 pairs) ----
            float2* dst = (mat == 0) ? g_Qp : g_Kp;
#pragma unroll
            for (int mt = 0; mt < 2; mt++)
#pragma unroll
                for (int hf = 0; hf < 2; hf++) {
                    int rr = mw * 32 + mt * 16 + hf * 8 + gid;
                    int tok = m0 + rr, bbv = tok >> 9, srow = tok & 511;
                    size_t rowb = ((size_t)(bbv * NH_ + hq) * S_ + srow) << 6;
#pragma unroll
                    for (int nt = 0; nt < 4; nt++) {
                        float x = tf32r(c[mt][nt][hf * 2 + 0]);
                        float y = tf32r(c[mt][nt][hf * 2 + 1]);
                        float ox = __shfl_xor_sync(0xffffffffu, x, 2);
                        float oy = __shfl_xor_sync(0xffffffffu, y, 2);
                        if (tig < 2)
                            *(float4*)&dst[rowb + 16 * nw + 4 * nt + 2 * tig] =
                                make_float4(x, ox, y, oy);
                    }
                }
        } else {
            // ---- V: transpose + pack by kv via shfl_xor 16 ----
#pragma unroll
            for (int mt = 0; mt < 2; mt++)
#pragma unroll
                for (int hf = 0; hf < 2; hf++) {
                    int rr = mw * 32 + mt * 16 + hf * 8 + gid;
                    int tok = m0 + rr, bbv = tok >> 9, srow = tok & 511;
                    int k2 = ((srow >> 3) << 2) | (srow & 3);
#pragma unroll
                    for (int nt = 0; nt < 4; nt++) {
                        float x = tf32r(c[mt][nt][hf * 2 + 0]);
                        float y = tf32r(c[mt][nt][hf * 2 + 1]);
                        float ox = __shfl_xor_sync(0xffffffffu, x, 16);
                        float oy = __shfl_xor_sync(0xffffffffu, y, 16);
                        if ((lane & 16) == 0) {
                            int d0 = nw * 32 + nt * 8 + 2 * tig;
                            size_t base = ((size_t)(bbv * NH_ + hq) * H_ + d0) << 8;
                            g_Vtp[base + k2]       = make_float2(x, ox);
                            g_Vtp[base + 256 + k2] = make_float2(y, oy);
                        }
                    }
                }
        }
    }
}

// =============================================================================
// Kernel 2: flash attention, tf32 MMA, all operands pre-packed in gmem.
// grid = (8 q-tiles, NH, B), 256 threads (8 warps: 4m x 2n).
// smem 107520 B: Qp 64x68 f2, Kp 64x68 f2 (Ps 64x68 floats aliased),
// Vtp 128x36 f2, rmax/rsum [2][64].  2 CTAs/SM.
// =============================================================================
__global__ void __launch_bounds__(256, 2) attn_kernel(const int* __restrict__ mask)
{
    extern __shared__ float sm[];
    float2* Qp   = (float2*)sm;                 // floats [0, 8704)
    float2* Kp   = (float2*)(sm + 8704);        // floats [8704, 17408)
    float*  Ps   = sm + 8704;                   // alias on Kp (64 x 68 floats)
    float2* Vtp  = (float2*)(sm + 17408);       // floats [17408, 26624)
    float*  rmax = sm + 26624;
    float*  rsum = sm + 26752;

    const int tid = threadIdx.x, lane = tid & 31, wid = tid >> 5;
    const int gid = lane >> 2, tig = lane & 3;
    const int mw = wid & 3, nw = wid >> 2;
    const int q0 = blockIdx.x * 64;
    const int hq = blockIdx.y, bb = blockIdx.z;
    const int bh = bb * NH_ + hq;
    const int r0 = mw * 16 + gid;

    // Q tile: 64 rows x 64 pairs (FIXED: full row coverage)
#pragma unroll
    for (int t = 0; t < 8; t++) {
        int idx = tid + t * 256;
        int r = idx >> 5, sl = idx & 31;
        float4 v = *(const float4*)&g_Qp[(((size_t)bh * S_ + q0 + r) << 6) + sl * 2];
        *(float4*)&Qp[r * 68 + sl * 2] = v;
    }

    float O[8][4];
#pragma unroll
    for (int nt = 0; nt < 8; nt++)
#pragma unroll
        for (int j = 0; j < 4; j++) O[nt][j] = 0.0f;
    float m0v = -1e30f, m1v = -1e30f, l0 = 0.0f, l1 = 0.0f;

    for (int kt = 0; kt < 8; kt++) {
        __syncthreads();
        const int k0 = kt * 64;
        // K tile: 64 rows x 64 pairs (FIXED)
#pragma unroll
        for (int t = 0; t < 8; t++) {
            int idx = tid + t * 256;
            int r = idx >> 5, sl = idx & 31;
            float4 v = *(const float4*)&g_Kp[(((size_t)bh * S_ + k0 + r) << 6) + sl * 2];
            *(float4*)&Kp[r * 68 + sl * 2] = v;
        }
        // V tile: 128 d-rows x 32 pairs (FIXED)
#pragma unroll
        for (int t = 0; t < 8; t++) {
            int idx = tid + t * 256;
            int r = idx >> 4, sl = idx & 15;
            float4 v = *(const float4*)&g_Vtp[(((size_t)bh * H_ + r) << 8) + (k0 >> 1) + sl * 2];
            *(float4*)&Vtp[r * 36 + sl * 2] = v;
        }
        __syncthreads();

        // ---- S = Q K^T ----
        float c[4][4];
#pragma unroll
        for (int nt = 0; nt < 4; nt++)
#pragma unroll
            for (int j = 0; j < 4; j++) c[nt][j] = 0.0f;
#pragma unroll
        for (int s = 0; s < 16; s++) {
            float2 pa = Qp[(r0)     * 68 + 4 * s + tig];
            float2 pb = Qp[(r0 + 8) * 68 + 4 * s + tig];
#pragma unroll
            for (int nt = 0; nt < 4; nt++) {
                float2 kb = Kp[(nw * 32 + nt * 8 + gid) * 68 + 4 * s + tig];
                mma_tf32(c[nt], fu(pa.x), fu(pb.x), fu(pa.y), fu(pb.y), fu(kb.x), fu(kb.y));
            }
        }

        // ---- mask + row max ----
        float mx0 = -1e30f, mx1 = -1e30f;
#pragma unroll
        for (int nt = 0; nt < 4; nt++) {
            int kc = k0 + nw * 32 + nt * 8 + 2 * tig;
            int2 mk0 = *(const int2*)&mask[((size_t)bb * S_ + (q0 + r0)) * S_ + kc];
            int2 mk1 = *(const int2*)&mask[((size_t)bb * S_ + (q0 + r0 + 8)) * S_ + kc];
            if (mk0.x == 0) c[nt][0] = NEG_INF_;
            if (mk0.y == 0) c[nt][1] = NEG_INF_;
            if (mk1.x == 0) c[nt][2] = NEG_INF_;
            if (mk1.y == 0) c[nt][3] = NEG_INF_;
            mx0 = fmaxf(mx0, fmaxf(c[nt][0], c[nt][1]));
            mx1 = fmaxf(mx1, fmaxf(c[nt][2], c[nt][3]));
        }
        mx0 = fmaxf(mx0, __shfl_xor_sync(0xffffffffu, mx0, 1));
        mx0 = fmaxf(mx0, __shfl_xor_sync(0xffffffffu, mx0, 2));
        mx1 = fmaxf(mx1, __shfl_xor_sync(0xffffffffu, mx1, 1));
        mx1 = fmaxf(mx1, __shfl_xor_sync(0xffffffffu, mx1, 2));
        if (tig == 0) {
            rmax[nw * 64 + r0]     = mx0;
            rmax[nw * 64 + r0 + 8] = mx1;
        }
        __syncthreads();               // rmax ready; Kp reads done -> Ps writes safe

        float nm0 = fmaxf(m0v, fmaxf(rmax[r0],     rmax[64 + r0]));
        float nm1 = fmaxf(m1v, fmaxf(rmax[r0 + 8], rmax[64 + r0 + 8]));
        float al0 = __expf(m0v - nm0), al1 = __expf(m1v - nm1);
        m0v = nm0; m1v = nm1;

        float s0 = 0.0f, s1 = 0.0f;
#pragma unroll
        for (int nt = 0; nt < 4; nt++) {
            float p0 = __expf(c[nt][0] - nm0);
            float p1 = __expf(c[nt][1] - nm0);
            float p2 = __expf(c[nt][2] - nm1);
            float p3 = __expf(c[nt][3] - nm1);
            s0 += p0 + p1; s1 += p2 + p3;
            int col = nw * 32 + nt * 8 + 2 * tig;
            *(float2*)&Ps[(r0)     * 68 + col] = make_float2(tf32r(p0), tf32r(p1));
            *(float2*)&Ps[(r0 + 8) * 68 + col] = make_float2(tf32r(p2), tf32r(p3));
        }
        s0 += __shfl_xor_sync(0xffffffffu, s0, 1);
        s0 += __shfl_xor_sync(0xffffffffu, s0, 2);
        s1 += __shfl_xor_sync(0xffffffffu, s1, 1);
        s1 += __shfl_xor_sync(0xffffffffu, s1, 2);
        if (tig == 0) {
            rsum[nw * 64 + r0]     = s0;
            rsum[nw * 64 + r0 + 8] = s1;
        }
#pragma unroll
        for (int nt = 0; nt < 8; nt++) {
            O[nt][0] *= al0; O[nt][1] *= al0;
            O[nt][2] *= al1; O[nt][3] *= al1;
        }
        __syncthreads();               // Ps + rsum visible

        l0 = l0 * al0 + rsum[r0]     + rsum[64 + r0];
        l1 = l1 * al1 + rsum[r0 + 8] + rsum[64 + r0 + 8];

        // ---- O += P @ V (V pre-transposed & packed) ----
#pragma unroll
        for (int ks = 0; ks < 8; ks++) {
            unsigned a0 = fu(Ps[(r0)     * 68 + 8 * ks + tig]);
            unsigned a1 = fu(Ps[(r0 + 8) * 68 + 8 * ks + tig]);
            unsigned a2 = fu(Ps[(r0)     * 68 + 8 * ks + tig + 4]);
            unsigned a3 = fu(Ps[(r0 + 8) * 68 + 8 * ks + tig + 4]);
#pragma unroll
            for (int nt = 0; nt < 8; nt++) {
                float2 vb = Vtp[(nw * 64 + nt * 8 + gid) * 36 + 4 * ks + tig];
                mma_tf32(O[nt], a0, a1, a2, a3, fu(vb.x), fu(vb.y));
            }
        }
    }

    // ---- normalize, round tf32, pack ctx (pairs along nhh) ----
    float inv0 = 1.0f / l0, inv1 = 1.0f / l1;
#pragma unroll
    for (int nt = 0; nt < 8; nt++) {
        int cblk = hq * 16 + nw * 8 + nt;
        float x = tf32r(O[nt][0] * inv0), y = tf32r(O[nt][1] * inv0);
        float ox = __shfl_xor_sync(0xffffffffu, x, 2);
        float oy = __shfl_xor_sync(0xffffffffu, y, 2);
        if (tig < 2)
            *(float4*)&g_ctxp[(((size_t)bb * S_ + q0 + r0) << 8) + 4 * cblk + 2 * tig] =
                make_float4(x, ox, y, oy);
        x = tf32r(O[nt][2] * inv1); y = tf32r(O[nt][3] * inv1);
        ox = __shfl_xor_sync(0xffffffffu, x, 2);
        oy = __shfl_xor_sync(0xffffffffu, y, 2);
        if (tig < 2)
            *(float4*)&g_ctxp[(((size_t)bb * S_ + q0 + r0 + 8) << 8) + 4 * cblk + 2 * tig] =
                make_float4(x, ox, y, oy);
    }
}

// =============================================================================
// Kernel 3: out = ctx @ Wo + enc, LayerNorm.  tf32 MMA, 4 k-chunks of 128.
// CTA = 64 tokens x N=128; 8 warps (2m x 4n).
// smem 104448 B: Ap 64x68 f2 + Ws 128x68 f2; Cs (64x132 f) aliases Ap.
// =============================================================================
__global__ void __launch_bounds__(256, 2) out_kernel(
    const float* __restrict__ enc, const float* __restrict__ gamma,
    const float* __restrict__ beta, float* __restrict__ out)
{
    extern __shared__ float sm[];
    float2* Ap = (float2*)sm;                   // 64 x 68 pairs
    float2* Ws = (float2*)(sm + 8704);          // 128 x 68 pairs
    float*  Cs = sm;                            // alias Ap: 64 x 132 floats

    const int tid = threadIdx.x, lane = tid & 31, wid = tid >> 5;
    const int gid = lane >> 2, tig = lane & 3;
    const int mw = wid & 1, nw = wid >> 1;
    const int m0 = blockIdx.x * 64;
    const int r0 = mw * 32 + gid;

    float c[2][4][4];
#pragma unroll
    for (int mt = 0; mt < 2; mt++)
#pragma unroll
        for (int nt = 0; nt < 4; nt++)
#pragma unroll
            for (int j = 0; j < 4; j++) c[mt][nt][j] = 0.0f;

    for (int kc = 0; kc < 4; kc++) {
        __syncthreads();
        // ctx chunk: 64 rows x 64 pairs (FIXED)
#pragma unroll
        for (int t = 0; t < 8; t++) {
            int idx = tid + t * 256;
            int r = idx >> 5, sl = idx & 31;
            float4 v = *(const float4*)&g_ctxp[(((size_t)(m0 + r)) << 8) + kc * 64 + sl * 2];
            *(float4*)&Ap[r * 68 + sl * 2] = v;
        }
        // Wo chunk: 128 rows x 64 pairs (FIXED)
#pragma unroll
        for (int t = 0; t < 16; t++) {
            int idx = tid + t * 256;
            int r = idx >> 5, sl = idx & 31;
            float4 v = *(const float4*)&g_Wop[((size_t)r << 8) + kc * 64 + sl * 2];
            *(float4*)&Ws[r * 68 + sl * 2] = v;
        }
        __syncthreads();
#pragma unroll
        for (int s = 0; s < 16; s++) {
            float2 a00 = Ap[(r0)      * 68 + 4 * s + tig];
            float2 a01 = Ap[(r0 + 8)  * 68 + 4 * s + tig];
            float2 a10 = Ap[(r0 + 16) * 68 + 4 * s + tig];
            float2 a11 = Ap[(r0 + 24) * 68 + 4 * s + tig];
#pragma unroll
            for (int nt = 0; nt < 4; nt++) {
                float2 b = Ws[(nw * 32 + nt * 8 + gid) * 68 + 4 * s + tig];
                mma_tf32(c[0][nt], fu(a00.x), fu(a01.x), fu(a00.y), fu(a01.y), fu(b.x), fu(b.y));
                mma_tf32(c[1][nt], fu(a10.x), fu(a11.x), fu(a10.y), fu(a11.y), fu(b.x), fu(b.y));
            }
        }
    }
    __syncthreads();                    // done with Ap -> reuse as Cs

#pragma unroll
    for (int mt = 0; mt < 2; mt++)
#pragma unroll
        for (int hf = 0; hf < 2; hf++) {
            int rr = mw * 32 + mt * 16 + hf * 8 + gid;
#pragma unroll
            for (int nt = 0; nt < 4; nt++) {
                int col = nw * 32 + nt * 8 + 2 * tig;
                *(float2*)&Cs[rr * 132 + col] =
                    make_float2(c[mt][nt][hf * 2 + 0], c[mt][nt][hf * 2 + 1]);
            }
        }
    __syncthreads();

    // ---- LayerNorm: 4 threads per row, 32 cols each ----
    const int row = tid >> 2, q = tid & 3;
    float x[32];
    float ssum = 0.0f, ssq = 0.0f;
#pragma unroll
    for (int i = 0; i < 8; i++) {
        float4 v = *(float4*)&Cs[row * 132 + q * 32 + i * 4];
        float4 e = *(const float4*)&enc[(size_t)(m0 + row) * H_ + q * 32 + i * 4];
        x[4 * i + 0] = v.x + e.x; x[4 * i + 1] = v.y + e.y;
        x[4 * i + 2] = v.z + e.z; x[4 * i + 3] = v.w + e.w;
#pragma unroll
        for (int j = 0; j < 4; j++) {
            ssum += x[4 * i + j];
            ssq  += x[4 * i + j] * x[4 * i + j];
        }
    }
    ssum += __shfl_xor_sync(0xffffffffu, ssum, 1);
    ssum += __shfl_xor_sync(0xffffffffu, ssum, 2);
    ssq  += __shfl_xor_sync(0xffffffffu, ssq,  1);
    ssq  += __shfl_xor_sync(0xffffffffu, ssq,  2);
    float mean = ssum * (1.0f / 128.0f);
    float var  = ssq * (1.0f / 128.0f) - mean * mean;
    float rstd = rsqrtf(var + 1e-6f);

#pragma unroll
    for (int i = 0; i < 8; i++) {
        float4 g  = *(const float4*)&gamma[q * 32 + i * 4];
        float4 be = *(const float4*)&beta[q * 32 + i * 4];
        float4 y = make_float4((x[4 * i + 0] - mean) * rstd * g.x + be.x,
                               (x[4 * i + 1] - mean) * rstd * g.y + be.y,
                               (x[4 * i + 2] - mean) * rstd * g.z + be.z,
                               (x[4 * i + 3] - mean) * rstd * g.w + be.w);
        *(float4*)&out[(size_t)(m0 + row) * H_ + q * 32 + i * 4] = y;
    }
}

// =============================================================================
extern "C" void kernel_launch(void* const* d_in, const int* in_sizes, int n_in,
                              void* d_out, int out_size)
{
    const float* enc   = (const float*)d_in[0];
    const int*   mask  = (const int*)  d_in[1];
    const float* Wq    = (const float*)d_in[2];
    const float* Wk    = (const float*)d_in[3];
    const float* Wv    = (const float*)d_in[4];
    const float* Wo    = (const float*)d_in[5];
    const float* gamma = (const float*)d_in[6];
    const float* beta  = (const float*)d_in[7];
    float* out = (float*)d_out;

    prep_kernel<<<512, 256>>>(Wq, Wk, Wv, Wo);

    const int smem1 = (64 * 68 + 128 * 68) * 2 * (int)sizeof(float);  // 104448 B
    cudaFuncSetAttribute(qkv_kernel, cudaFuncAttributeMaxDynamicSharedMemorySize, smem1);
    qkv_kernel<<<(B_ * S_) / 64, 256, smem1>>>(enc);

    const int smem2 = 26880 * (int)sizeof(float);                     // 107520 B
    cudaFuncSetAttribute(attn_kernel, cudaFuncAttributeMaxDynamicSharedMemorySize, smem2);
    dim3 g2(S_ / 64, NH_, B_);
    attn_kernel<<<g2, 256, smem2>>>(mask);

    const int smem3 = (64 * 68 + 128 * 68) * 2 * (int)sizeof(float);  // 104448 B
    cudaFuncSetAttribute(out_kernel, cudaFuncAttributeMaxDynamicSharedMemorySize, smem3);
    out_kernel<<<(B_ * S_) / 64, 256, smem3>>>(enc, gamma, beta, out);
}

// round 8
// speedup vs baseline: 2.1018x; 1.8589x over previous
#include <cuda_runtime.h>
#include <cuda_fp16.h>

#define B_    64
#define S_    512
#define H_    128
#define NH_   4
#define NHH_  512
#define QSCALE 0.08838834764831845f   /* 1/sqrt(128) */
#define NEG_INF_ -1e9f

// ---------------- packed fp16 scratch ----------------------------------------
// "Unit" = float2 (8B) = 2 half2: unit u holds (h2[j], h2[j+4]) with
// j = 8*(u>>2) + (u&3).  h2[j] = (T[2j], T[2j+1]) along the MMA k-dim.
// This makes every m16n8k16 fragment half exactly one LDS.64.
__device__ float2 g_Qh [(size_t)B_ * NH_ * S_ * 32];      // [bh][s][32u]  (k=d 128)
__device__ float2 g_Kh [(size_t)B_ * NH_ * S_ * 32];      // [bh][s][32u]
__device__ float2 g_Vth[(size_t)B_ * NH_ * H_ * 8 * 16];  // [bh][d][kt8][16u] (k=kv 64/tile)
__device__ float2 g_ctxh[(size_t)B_ * S_ * 4 * 32];       // [tok][kc4][32u]   (k=128/chunk)
__device__ float2 g_Wh [3 * 512 * 32];                    // [mat][n][32u], Wq*QSCALE folded
__device__ float2 g_Woh[128 * 4 * 32];                    // [n][kc4][32u]

// ---------------- helpers ----------------------------------------------------
__device__ __forceinline__ unsigned h2u(float x, float y) {
    __half2 h = __floats2half2_rn(x, y);
    return *reinterpret_cast<unsigned*>(&h);
}
__device__ __forceinline__ unsigned hh2u(__half x, __half y) {
    __half2 h = __halves2half2(x, y);
    return *reinterpret_cast<unsigned*>(&h);
}
__device__ __forceinline__ unsigned fu(float x) { return __float_as_uint(x); }
__device__ __forceinline__ float    uf(unsigned u) { return __uint_as_float(u); }

__device__ __forceinline__ void mma_f16(float c[4],
                                        unsigned a0, unsigned a1, unsigned a2, unsigned a3,
                                        unsigned b0, unsigned b1) {
    asm volatile(
        "mma.sync.aligned.m16n8k16.row.col.f32.f16.f16.f32 "
        "{%0,%1,%2,%3}, {%4,%5,%6,%7}, {%8,%9}, {%0,%1,%2,%3};"
        : "+f"(c[0]), "+f"(c[1]), "+f"(c[2]), "+f"(c[3])
        : "r"(a0), "r"(a1), "r"(a2), "r"(a3), "r"(b0), "r"(b1));
}

// =============================================================================
// Kernel 0: pack weights to fp16 packed-unit layout. 65536 threads.
// =============================================================================
__global__ void __launch_bounds__(256) prep_kernel(
    const float* __restrict__ Wq, const float* __restrict__ Wk,
    const float* __restrict__ Wv, const float* __restrict__ Wo)
{
    int idx = blockIdx.x * 256 + threadIdx.x;
    if (idx < 3 * 512 * 32) {
        int u = idx & 31, n = (idx >> 5) & 511, mat = idx >> 14;
        const float* W = (mat == 0) ? Wq : (mat == 1) ? Wk : Wv;
        float scl = (mat == 0) ? QSCALE : 1.0f;
        int j = 8 * (u >> 2) + (u & 3);
        float2 v;
        v.x = uf(h2u(W[(size_t)(2 * j)     * NHH_ + n] * scl,
                     W[(size_t)(2 * j + 1) * NHH_ + n] * scl));
        v.y = uf(h2u(W[(size_t)(2 * j + 8) * NHH_ + n] * scl,
                     W[(size_t)(2 * j + 9) * NHH_ + n] * scl));
        g_Wh[idx] = v;
    } else {
        int i2 = idx - 3 * 512 * 32;     // 128*4*32 = 16384
        int u = i2 & 31, kc = (i2 >> 5) & 3, n = i2 >> 7;
        int j = 8 * (u >> 2) + (u & 3);
        int kb = kc * 128;
        float2 v;
        v.x = uf(h2u(Wo[(size_t)(kb + 2 * j)     * H_ + n],
                     Wo[(size_t)(kb + 2 * j + 1) * H_ + n]));
        v.y = uf(h2u(Wo[(size_t)(kb + 2 * j + 8) * H_ + n],
                     Wo[(size_t)(kb + 2 * j + 9) * H_ + n]));
        g_Woh[(size_t)(n * 4 + kc) * 32 + u] = v;
    }
}

// =============================================================================
// Kernel 1: QKV projection, m-resident, fp16 MMA (m16n8k16).
// CTA = 64 tokens; 12 (mat,hq) chunks of 128 n-cols; 8 warps (2m x 4n).
// smem 72192 B: Ap 64x36u, Ws 128x36u, Vst 64x132 halfs.
// =============================================================================
__global__ void __launch_bounds__(256, 2) qkv_kernel(const float* __restrict__ enc)
{
    extern __shared__ float sm[];
    float2* Ap  = (float2*)sm;              // 64 x 36 units  (floats [0,4608))
    float2* Ws  = (float2*)(sm + 4608);     // 128 x 36 units (floats [4608,13824))
    __half* Vst = (__half*)(sm + 13824);    // 64 x 132 halfs (16896 B)

    const int tid = threadIdx.x, lane = tid & 31, wid = tid >> 5;
    const int gid = lane >> 2, tig = lane & 3;
    const int mw = wid & 1, nw = wid >> 1;
    const int m0 = blockIdx.x * 64;
    const int r0 = mw * 32 + gid;
    __half2* Aph2 = (__half2*)Ap;

    // ---- pack enc tile to fp16 units ----
#pragma unroll
    for (int t = 0; t < 8; t++) {
        int idx = tid + t * 256;
        int r = idx >> 5, sl = idx & 31;                 // float4 = k 4sl..4sl+3
        float4 a = *(const float4*)&enc[(size_t)(m0 + r) * H_ + sl * 4];
        int j0 = 2 * sl, j1 = 2 * sl + 1;
        int u0 = 4 * (j0 >> 3) + (j0 & 3), c0 = (j0 >> 2) & 1;
        int u1 = 4 * (j1 >> 3) + (j1 & 3), c1 = (j1 >> 2) & 1;
        __half2 h0 = __floats2half2_rn(a.x, a.y);
        __half2 h1 = __floats2half2_rn(a.z, a.w);
        Aph2[(r * 36 + u0) * 2 + c0] = h0;
        Aph2[(r * 36 + u1) * 2 + c1] = h1;
    }

    for (int ch = 0; ch < 12; ch++) {
        const int mat = ch >> 2, hq = ch & 3;
        __syncthreads();
        // fill W chunk: 128 rows x 32 units = 2048 float4
#pragma unroll
        for (int t = 0; t < 8; t++) {
            int idx = tid + t * 256;
            int r = idx >> 4, q = idx & 15;
            float4 w = *(const float4*)&g_Wh[(size_t)((mat * 512 + hq * 128 + r) * 32) + 2 * q];
            *(float4*)&Ws[r * 36 + 2 * q] = w;
        }
        __syncthreads();

        float c[2][4][4];
#pragma unroll
        for (int mt = 0; mt < 2; mt++)
#pragma unroll
            for (int nt = 0; nt < 4; nt++)
#pragma unroll
                for (int j = 0; j < 4; j++) c[mt][nt][j] = 0.0f;

#pragma unroll
        for (int s2 = 0; s2 < 8; s2++) {
            float2 A0  = Ap[(r0)      * 36 + 4 * s2 + tig];
            float2 A8  = Ap[(r0 + 8)  * 36 + 4 * s2 + tig];
            float2 A16 = Ap[(r0 + 16) * 36 + 4 * s2 + tig];
            float2 A24 = Ap[(r0 + 24) * 36 + 4 * s2 + tig];
#pragma unroll
            for (int nt = 0; nt < 4; nt++) {
                float2 Bv = Ws[(nw * 32 + nt * 8 + gid) * 36 + 4 * s2 + tig];
                mma_f16(c[0][nt], fu(A0.x),  fu(A8.x),  fu(A0.y),  fu(A8.y),  fu(Bv.x), fu(Bv.y));
                mma_f16(c[1][nt], fu(A16.x), fu(A24.x), fu(A16.y), fu(A24.y), fu(Bv.x), fu(Bv.y));
            }
        }

        if (mat < 2) {
            // ---- Q/K: nt-pairs pack into units directly (no shuffles) ----
            float2* dst = (mat == 0) ? g_Qh : g_Kh;
#pragma unroll
            for (int mt = 0; mt < 2; mt++)
#pragma unroll
                for (int hf = 0; hf < 2; hf++) {
                    int rr = mw * 32 + mt * 16 + hf * 8 + gid;
                    int tok = m0 + rr, bbv = tok >> 9, srow = tok & 511;
                    size_t base = ((size_t)(bbv * NH_ + hq) * S_ + srow) * 32;
#pragma unroll
                    for (int p = 0; p < 2; p++) {
                        float2 v;
                        v.x = uf(h2u(c[mt][2 * p][hf * 2],     c[mt][2 * p][hf * 2 + 1]));
                        v.y = uf(h2u(c[mt][2 * p + 1][hf * 2], c[mt][2 * p + 1][hf * 2 + 1]));
                        dst[base + 8 * nw + 4 * p + tig] = v;
                    }
                }
        } else {
            // ---- V: stage in smem, transpose+repack to g_Vth ----
            __syncthreads();
#pragma unroll
            for (int mt = 0; mt < 2; mt++)
#pragma unroll
                for (int hf = 0; hf < 2; hf++) {
                    int rr = mw * 32 + mt * 16 + hf * 8 + gid;   // local token 0..63
#pragma unroll
                    for (int nt = 0; nt < 4; nt++) {
                        int jd = 16 * nw + 4 * nt + tig;          // d-half2 index
                        *(__half2*)&Vst[rr * 132 + 2 * jd] =
                            __floats2half2_rn(c[mt][nt][hf * 2], c[mt][nt][hf * 2 + 1]);
                    }
                }
            __syncthreads();
            const int bbv = m0 >> 9, kt = (m0 & 511) >> 6;
            size_t vbase = (size_t)(bbv * NH_ + hq) * H_;
#pragma unroll
            for (int t = 0; t < 8; t++) {
                int idx = tid + t * 256;
                int d = idx >> 4, u = idx & 15;
                int j = 8 * (u >> 2) + (u & 3);
                float2 o;
                o.x = uf(hh2u(Vst[(2 * j)     * 132 + d], Vst[(2 * j + 1) * 132 + d]));
                o.y = uf(hh2u(Vst[(2 * j + 8) * 132 + d], Vst[(2 * j + 9) * 132 + d]));
                g_Vth[((vbase + d) * 8 + kt) * 16 + u] = o;
            }
        }
    }
}

// =============================================================================
// Kernel 2: flash attention, fp16 MMA. grid = (8 q-tiles, NH, B), 8 warps 4m x 2n.
// smem 68608 B: Qh 64x36u, Kh 64x36u, Vth 128x20u, Ps 64x20u, rmax/rsum.
// =============================================================================
__global__ void __launch_bounds__(256, 2) attn_kernel(const int* __restrict__ mask)
{
    extern __shared__ float sm[];
    float2* Qh   = (float2*)sm;             // floats [0,4608)
    float2* Kh   = (float2*)(sm + 4608);    // [4608,9216)
    float2* Vth  = (float2*)(sm + 9216);    // 128x20u  [9216,14336)
    float2* Ps   = (float2*)(sm + 14336);   // 64x20u   [14336,16896)
    float*  rmax = sm + 16896;
    float*  rsum = sm + 17024;

    const int tid = threadIdx.x, lane = tid & 31, wid = tid >> 5;
    const int gid = lane >> 2, tig = lane & 3;
    const int mw = wid & 3, nw = wid >> 2;
    const int q0 = blockIdx.x * 64;
    const int hq = blockIdx.y, bb = blockIdx.z;
    const int bh = bb * NH_ + hq;
    const int r0 = mw * 16 + gid;

    // Q tile: 64 rows x 32 units = 1024 float4
#pragma unroll
    for (int t = 0; t < 4; t++) {
        int idx = tid + t * 256;
        int r = idx >> 4, q = idx & 15;
        float4 v = *(const float4*)&g_Qh[((size_t)bh * S_ + q0 + r) * 32 + 2 * q];
        *(float4*)&Qh[r * 36 + 2 * q] = v;
    }

    float O[8][4];
#pragma unroll
    for (int nt = 0; nt < 8; nt++)
#pragma unroll
        for (int j = 0; j < 4; j++) O[nt][j] = 0.0f;
    float m0v = -1e30f, m1v = -1e30f, l0 = 0.0f, l1 = 0.0f;

    for (int kt = 0; kt < 8; kt++) {
        __syncthreads();
        const int k0 = kt * 64;
#pragma unroll
        for (int t = 0; t < 4; t++) {
            int idx = tid + t * 256;
            int r = idx >> 4, q = idx & 15;
            float4 v = *(const float4*)&g_Kh[((size_t)bh * S_ + k0 + r) * 32 + 2 * q];
            *(float4*)&Kh[r * 36 + 2 * q] = v;
        }
#pragma unroll
        for (int t = 0; t < 4; t++) {
            int idx = tid + t * 256;
            int d = idx >> 3, q = idx & 7;
            float4 v = *(const float4*)&g_Vth[(((size_t)bh * H_ + d) * 8 + kt) * 16 + 2 * q];
            *(float4*)&Vth[d * 20 + 2 * q] = v;
        }
        __syncthreads();

        // ---- S = Q K^T ----
        float c[4][4];
#pragma unroll
        for (int nt = 0; nt < 4; nt++)
#pragma unroll
            for (int j = 0; j < 4; j++) c[nt][j] = 0.0f;
#pragma unroll
        for (int s2 = 0; s2 < 8; s2++) {
            float2 A0 = Qh[(r0)     * 36 + 4 * s2 + tig];
            float2 A8 = Qh[(r0 + 8) * 36 + 4 * s2 + tig];
#pragma unroll
            for (int nt = 0; nt < 4; nt++) {
                float2 Bv = Kh[(nw * 32 + nt * 8 + gid) * 36 + 4 * s2 + tig];
                mma_f16(c[nt], fu(A0.x), fu(A8.x), fu(A0.y), fu(A8.y), fu(Bv.x), fu(Bv.y));
            }
        }

        // ---- mask + row max ----
        float mx0 = -1e30f, mx1 = -1e30f;
#pragma unroll
        for (int nt = 0; nt < 4; nt++) {
            int kc = k0 + nw * 32 + nt * 8 + 2 * tig;
            int2 mk0 = *(const int2*)&mask[((size_t)bb * S_ + (q0 + r0)) * S_ + kc];
            int2 mk1 = *(const int2*)&mask[((size_t)bb * S_ + (q0 + r0 + 8)) * S_ + kc];
            if (mk0.x == 0) c[nt][0] = NEG_INF_;
            if (mk0.y == 0) c[nt][1] = NEG_INF_;
            if (mk1.x == 0) c[nt][2] = NEG_INF_;
            if (mk1.y == 0) c[nt][3] = NEG_INF_;
            mx0 = fmaxf(mx0, fmaxf(c[nt][0], c[nt][1]));
            mx1 = fmaxf(mx1, fmaxf(c[nt][2], c[nt][3]));
        }
        mx0 = fmaxf(mx0, __shfl_xor_sync(0xffffffffu, mx0, 1));
        mx0 = fmaxf(mx0, __shfl_xor_sync(0xffffffffu, mx0, 2));
        mx1 = fmaxf(mx1, __shfl_xor_sync(0xffffffffu, mx1, 1));
        mx1 = fmaxf(mx1, __shfl_xor_sync(0xffffffffu, mx1, 2));
        if (tig == 0) {
            rmax[nw * 64 + r0]     = mx0;
            rmax[nw * 64 + r0 + 8] = mx1;
        }
        __syncthreads();

        float nm0 = fmaxf(m0v, fmaxf(rmax[r0],     rmax[64 + r0]));
        float nm1 = fmaxf(m1v, fmaxf(rmax[r0 + 8], rmax[64 + r0 + 8]));
        float al0 = __expf(m0v - nm0), al1 = __expf(m1v - nm1);
        m0v = nm0; m1v = nm1;

        float s0 = 0.0f, s1 = 0.0f;
#pragma unroll
        for (int p = 0; p < 2; p++) {
            float e00 = __expf(c[2 * p][0] - nm0),     e01 = __expf(c[2 * p][1] - nm0);
            float e10 = __expf(c[2 * p + 1][0] - nm0), e11 = __expf(c[2 * p + 1][1] - nm0);
            float f00 = __expf(c[2 * p][2] - nm1),     f01 = __expf(c[2 * p][3] - nm1);
            float f10 = __expf(c[2 * p + 1][2] - nm1), f11 = __expf(c[2 * p + 1][3] - nm1);
            s0 += e00 + e01 + e10 + e11;
            s1 += f00 + f01 + f10 + f11;
            float2 v0, v1;
            v0.x = uf(h2u(e00, e01)); v0.y = uf(h2u(e10, e11));
            v1.x = uf(h2u(f00, f01)); v1.y = uf(h2u(f10, f11));
            Ps[(r0)     * 20 + 8 * nw + 4 * p + tig] = v0;
            Ps[(r0 + 8) * 20 + 8 * nw + 4 * p + tig] = v1;
        }
        s0 += __shfl_xor_sync(0xffffffffu, s0, 1);
        s0 += __shfl_xor_sync(0xffffffffu, s0, 2);
        s1 += __shfl_xor_sync(0xffffffffu, s1, 1);
        s1 += __shfl_xor_sync(0xffffffffu, s1, 2);
        if (tig == 0) {
            rsum[nw * 64 + r0]     = s0;
            rsum[nw * 64 + r0 + 8] = s1;
        }
#pragma unroll
        for (int nt = 0; nt < 8; nt++) {
            O[nt][0] *= al0; O[nt][1] *= al0;
            O[nt][2] *= al1; O[nt][3] *= al1;
        }
        __syncthreads();

        l0 = l0 * al0 + rsum[r0]     + rsum[64 + r0];
        l1 = l1 * al1 + rsum[r0 + 8] + rsum[64 + r0 + 8];

        // ---- O += P @ V ----
#pragma unroll
        for (int s2v = 0; s2v < 4; s2v++) {
            float2 A0 = Ps[(r0)     * 20 + 4 * s2v + tig];
            float2 A8 = Ps[(r0 + 8) * 20 + 4 * s2v + tig];
#pragma unroll
            for (int nt = 0; nt < 8; nt++) {
                float2 Bv = Vth[(nw * 64 + nt * 8 + gid) * 20 + 4 * s2v + tig];
                mma_f16(O[nt], fu(A0.x), fu(A8.x), fu(A0.y), fu(A8.y), fu(Bv.x), fu(Bv.y));
            }
        }
    }

    // ---- normalize, pack ctx units (no shuffles) ----
    float inv0 = 1.0f / l0, inv1 = 1.0f / l1;
    size_t cb0 = ((size_t)(bb * S_ + q0 + r0)     * 4 + hq) * 32;
    size_t cb1 = ((size_t)(bb * S_ + q0 + r0 + 8) * 4 + hq) * 32;
#pragma unroll
    for (int p = 0; p < 4; p++) {
        float2 v0, v1;
        v0.x = uf(h2u(O[2 * p][0] * inv0,     O[2 * p][1] * inv0));
        v0.y = uf(h2u(O[2 * p + 1][0] * inv0, O[2 * p + 1][1] * inv0));
        v1.x = uf(h2u(O[2 * p][2] * inv1,     O[2 * p][3] * inv1));
        v1.y = uf(h2u(O[2 * p + 1][2] * inv1, O[2 * p + 1][3] * inv1));
        g_ctxh[cb0 + 16 * nw + 4 * p + tig] = v0;
        g_ctxh[cb1 + 16 * nw + 4 * p + tig] = v1;
    }
}

// =============================================================================
// Kernel 3: out = ctx @ Wo + enc, LayerNorm. fp16 MMA, 4 k-chunks of 128.
// CTA = 64 tokens x N=128; 8 warps (2m x 4n). smem 55296 B.
// =============================================================================
__global__ void __launch_bounds__(256, 2) out_kernel(
    const float* __restrict__ enc, const float* __restrict__ gamma,
    const float* __restrict__ beta, float* __restrict__ out)
{
    extern __shared__ float sm[];
    float2* Ap = (float2*)sm;               // 64 x 36u
    float2* Ws = (float2*)(sm + 4608);      // 128 x 36u
    float*  Cs = sm;                        // alias: 64 x 132 floats (fits in 13824)

    const int tid = threadIdx.x, lane = tid & 31, wid = tid >> 5;
    const int gid = lane >> 2, tig = lane & 3;
    const int mw = wid & 1, nw = wid >> 1;
    const int m0 = blockIdx.x * 64;
    const int r0 = mw * 32 + gid;

    float c[2][4][4];
#pragma unroll
    for (int mt = 0; mt < 2; mt++)
#pragma unroll
        for (int nt = 0; nt < 4; nt++)
#pragma unroll
            for (int j = 0; j < 4; j++) c[mt][nt][j] = 0.0f;

    for (int kc = 0; kc < 4; kc++) {
        __syncthreads();
#pragma unroll
        for (int t = 0; t < 4; t++) {
            int idx = tid + t * 256;
            int r = idx >> 4, q = idx & 15;
            float4 v = *(const float4*)&g_ctxh[((size_t)(m0 + r) * 4 + kc) * 32 + 2 * q];
            *(float4*)&Ap[r * 36 + 2 * q] = v;
        }
#pragma unroll
        for (int t = 0; t < 8; t++) {
            int idx = tid + t * 256;
            int r = idx >> 4, q = idx & 15;
            float4 v = *(const float4*)&g_Woh[((size_t)r * 4 + kc) * 32 + 2 * q];
            *(float4*)&Ws[r * 36 + 2 * q] = v;
        }
        __syncthreads();
#pragma unroll
        for (int s2 = 0; s2 < 8; s2++) {
            float2 A0  = Ap[(r0)      * 36 + 4 * s2 + tig];
            float2 A8  = Ap[(r0 + 8)  * 36 + 4 * s2 + tig];
            float2 A16 = Ap[(r0 + 16) * 36 + 4 * s2 + tig];
            float2 A24 = Ap[(r0 + 24) * 36 + 4 * s2 + tig];
#pragma unroll
            for (int nt = 0; nt < 4; nt++) {
                float2 Bv = Ws[(nw * 32 + nt * 8 + gid) * 36 + 4 * s2 + tig];
                mma_f16(c[0][nt], fu(A0.x),  fu(A8.x),  fu(A0.y),  fu(A8.y),  fu(Bv.x), fu(Bv.y));
                mma_f16(c[1][nt], fu(A16.x), fu(A24.x), fu(A16.y), fu(A24.y), fu(Bv.x), fu(Bv.y));
            }
        }
    }
    __syncthreads();                    // done with Ap/Ws -> reuse as Cs

#pragma unroll
    for (int mt = 0; mt < 2; mt++)
#pragma unroll
        for (int hf = 0; hf < 2; hf++) {
            int rr = mw * 32 + mt * 16 + hf * 8 + gid;
#pragma unroll
            for (int nt = 0; nt < 4; nt++) {
                int col = nw * 32 + nt * 8 + 2 * tig;
                *(float2*)&Cs[rr * 132 + col] =
                    make_float2(c[mt][nt][hf * 2 + 0], c[mt][nt][hf * 2 + 1]);
            }
        }
    __syncthreads();

    // ---- LayerNorm: 4 threads per row, 32 cols each ----
    const int row = tid >> 2, q = tid & 3;
    float x[32];
    float ssum = 0.0f, ssq = 0.0f;
#pragma unroll
    for (int i = 0; i < 8; i++) {
        float4 v = *(float4*)&Cs[row * 132 + q * 32 + i * 4];
        float4 e = *(const float4*)&enc[(size_t)(m0 + row) * H_ + q * 32 + i * 4];
        x[4 * i + 0] = v.x + e.x; x[4 * i + 1] = v.y + e.y;
        x[4 * i + 2] = v.z + e.z; x[4 * i + 3] = v.w + e.w;
#pragma unroll
        for (int j = 0; j < 4; j++) {
            ssum += x[4 * i + j];
            ssq  += x[4 * i + j] * x[4 * i + j];
        }
    }
    ssum += __shfl_xor_sync(0xffffffffu, ssum, 1);
    ssum += __shfl_xor_sync(0xffffffffu, ssum, 2);
    ssq  += __shfl_xor_sync(0xffffffffu, ssq,  1);
    ssq  += __shfl_xor_sync(0xffffffffu, ssq,  2);
    float mean = ssum * (1.0f / 128.0f);
    float var  = ssq * (1.0f / 128.0f) - mean * mean;
    float rstd = rsqrtf(var + 1e-6f);

#pragma unroll
    for (int i = 0; i < 8; i++) {
        float4 g  = *(const float4*)&gamma[q * 32 + i * 4];
        float4 be = *(const float4*)&beta[q * 32 + i * 4];
        float4 y = make_float4((x[4 * i + 0] - mean) * rstd * g.x + be.x,
                               (x[4 * i + 1] - mean) * rstd * g.y + be.y,
                               (x[4 * i + 2] - mean) * rstd * g.z + be.z,
                               (x[4 * i + 3] - mean) * rstd * g.w + be.w);
        *(float4*)&out[(size_t)(m0 + row) * H_ + q * 32 + i * 4] = y;
    }
}

// =============================================================================
extern "C" void kernel_launch(void* const* d_in, const int* in_sizes, int n_in,
                              void* d_out, int out_size)
{
    const float* enc   = (const float*)d_in[0];
    const int*   mask  = (const int*)  d_in[1];
    const float* Wq    = (const float*)d_in[2];
    const float* Wk    = (const float*)d_in[3];
    const float* Wv    = (const float*)d_in[4];
    const float* Wo    = (const float*)d_in[5];
    const float* gamma = (const float*)d_in[6];
    const float* beta  = (const float*)d_in[7];
    float* out = (float*)d_out;

    prep_kernel<<<256, 256>>>(Wq, Wk, Wv, Wo);

    const int smem1 = 72192;
    cudaFuncSetAttribute(qkv_kernel, cudaFuncAttributeMaxDynamicSharedMemorySize, smem1);
    qkv_kernel<<<(B_ * S_) / 64, 256, smem1>>>(enc);

    const int smem2 = 68608;
    cudaFuncSetAttribute(attn_kernel, cudaFuncAttributeMaxDynamicSharedMemorySize, smem2);
    dim3 g2(S_ / 64, NH_, B_);
    attn_kernel<<<g2, 256, smem2>>>(mask);

    const int smem3 = 55296;
    cudaFuncSetAttribute(out_kernel, cudaFuncAttributeMaxDynamicSharedMemorySize, smem3);
    out_kernel<<<(B_ * S_) / 64, 256, smem3>>>(enc, gamma, beta, out);
}

// round 9
// speedup vs baseline: 2.3257x; 1.1065x over previous
#include <cuda_runtime.h>
#include <cuda_fp16.h>

#define B_    64
#define S_    512
#define H_    128
#define NH_   4
#define NHH_  512
#define QSCALE 0.08838834764831845f   /* 1/sqrt(128) */
#define NEG_INF_ -1e9f

// ---------------- packed fp16 scratch ----------------------------------------
// "Unit" = float2 (8B) = 2 half2: unit u holds (h2[j], h2[j+4]) with
// j = 8*(u>>2) + (u&3).  h2[j] = (T[2j], T[2j+1]) along the MMA k-dim.
__device__ float2 g_Qh [(size_t)B_ * NH_ * S_ * 32];      // [bh][s][32u]  (k=d 128)
__device__ float2 g_Kh [(size_t)B_ * NH_ * S_ * 32];      // [bh][s][32u]
__device__ float2 g_Vth[(size_t)B_ * NH_ * H_ * 4 * 32];  // [bh][d][kt4][32u] (k=kv 128/tile)
__device__ float2 g_ctxh[(size_t)B_ * S_ * 4 * 32];       // [tok][kc4][32u]
__device__ float2 g_Wh [3 * 512 * 32];                    // [mat][n][32u], Wq*QSCALE folded
__device__ float2 g_Woh[128 * 4 * 32];                    // [n][kc4][32u]

// ---------------- helpers ----------------------------------------------------
__device__ __forceinline__ unsigned h2u(float x, float y) {
    __half2 h = __floats2half2_rn(x, y);
    return *reinterpret_cast<unsigned*>(&h);
}
__device__ __forceinline__ unsigned hh2u(__half x, __half y) {
    __half2 h = __halves2half2(x, y);
    return *reinterpret_cast<unsigned*>(&h);
}
__device__ __forceinline__ unsigned fu(float x) { return __float_as_uint(x); }
__device__ __forceinline__ float    uf(unsigned u) { return __uint_as_float(u); }

__device__ __forceinline__ void mma_f16(float c[4],
                                        unsigned a0, unsigned a1, unsigned a2, unsigned a3,
                                        unsigned b0, unsigned b1) {
    asm volatile(
        "mma.sync.aligned.m16n8k16.row.col.f32.f16.f16.f32 "
        "{%0,%1,%2,%3}, {%4,%5,%6,%7}, {%8,%9}, {%0,%1,%2,%3};"
        : "+f"(c[0]), "+f"(c[1]), "+f"(c[2]), "+f"(c[3])
        : "r"(a0), "r"(a1), "r"(a2), "r"(a3), "r"(b0), "r"(b1));
}

__device__ __forceinline__ void cpa16(void* dst, const void* src) {
    unsigned d = (unsigned)__cvta_generic_to_shared(dst);
    asm volatile("cp.async.cg.shared.global [%0], [%1], 16;" :: "r"(d), "l"(src));
}
__device__ __forceinline__ void cp_commit() { asm volatile("cp.async.commit_group;"); }
template<int N> __device__ __forceinline__ void cp_wait() {
    asm volatile("cp.async.wait_group %0;" :: "n"(N));
}

// =============================================================================
// Kernel 0: pack weights to fp16 packed-unit layout. 65536 threads.
// =============================================================================
__global__ void __launch_bounds__(256) prep_kernel(
    const float* __restrict__ Wq, const float* __restrict__ Wk,
    const float* __restrict__ Wv, const float* __restrict__ Wo)
{
    int idx = blockIdx.x * 256 + threadIdx.x;
    if (idx < 3 * 512 * 32) {
        int u = idx & 31, n = (idx >> 5) & 511, mat = idx >> 14;
        const float* W = (mat == 0) ? Wq : (mat == 1) ? Wk : Wv;
        float scl = (mat == 0) ? QSCALE : 1.0f;
        int j = 8 * (u >> 2) + (u & 3);
        float2 v;
        v.x = uf(h2u(W[(size_t)(2 * j)     * NHH_ + n] * scl,
                     W[(size_t)(2 * j + 1) * NHH_ + n] * scl));
        v.y = uf(h2u(W[(size_t)(2 * j + 8) * NHH_ + n] * scl,
                     W[(size_t)(2 * j + 9) * NHH_ + n] * scl));
        g_Wh[idx] = v;
    } else {
        int i2 = idx - 3 * 512 * 32;
        int u = i2 & 31, kc = (i2 >> 5) & 3, n = i2 >> 7;
        int j = 8 * (u >> 2) + (u & 3);
        int kb = kc * 128;
        float2 v;
        v.x = uf(h2u(Wo[(size_t)(kb + 2 * j)     * H_ + n],
                     Wo[(size_t)(kb + 2 * j + 1) * H_ + n]));
        v.y = uf(h2u(Wo[(size_t)(kb + 2 * j + 8) * H_ + n],
                     Wo[(size_t)(kb + 2 * j + 9) * H_ + n]));
        g_Woh[(size_t)(n * 4 + kc) * 32 + u] = v;
    }
}

// =============================================================================
// Kernel 1: QKV projection, m-resident, fp16 MMA, DOUBLE-BUFFERED W prefetch.
// CTA = 64 tokens; 12 (mat,hq) chunks; 8 warps (2m x 4n).
// smem 109056 B: Ap 64x36u, Ws0/Ws1 128x36u each, Vst 64x132 halfs.
// =============================================================================
__global__ void __launch_bounds__(256, 2) qkv_kernel(const float* __restrict__ enc)
{
    extern __shared__ float sm[];
    float2* Ap  = (float2*)sm;              // [0,4608)
    float2* Ws0 = (float2*)(sm + 4608);     // [4608,13824)
    float2* Ws1 = (float2*)(sm + 13824);    // [13824,23040)
    __half* Vst = (__half*)(sm + 23040);    // 64x132 halfs (16896 B)

    const int tid = threadIdx.x, lane = tid & 31, wid = tid >> 5;
    const int gid = lane >> 2, tig = lane & 3;
    const int mw = wid & 1, nw = wid >> 1;
    const int m0 = blockIdx.x * 64;
    const int r0 = mw * 32 + gid;
    __half2* Aph2 = (__half2*)Ap;

    // ---- pack enc tile to fp16 units ----
#pragma unroll
    for (int t = 0; t < 8; t++) {
        int idx = tid + t * 256;
        int r = idx >> 5, sl = idx & 31;
        float4 a = *(const float4*)&enc[(size_t)(m0 + r) * H_ + sl * 4];
        int j0 = 2 * sl, j1 = 2 * sl + 1;
        int u0 = 4 * (j0 >> 3) + (j0 & 3), c0 = (j0 >> 2) & 1;
        int u1 = 4 * (j1 >> 3) + (j1 & 3), c1 = (j1 >> 2) & 1;
        Aph2[(r * 36 + u0) * 2 + c0] = __floats2half2_rn(a.x, a.y);
        Aph2[(r * 36 + u1) * 2 + c1] = __floats2half2_rn(a.z, a.w);
    }

    // prefetch chunk 0 into Ws0
#pragma unroll
    for (int t = 0; t < 8; t++) {
        int idx = tid + t * 256;
        int r = idx >> 4, q = idx & 15;
        cpa16(&Ws0[r * 36 + 2 * q], &g_Wh[(size_t)(r << 5) + 2 * q]);
    }
    cp_commit();

    for (int ch = 0; ch < 12; ch++) {
        const int mat = ch >> 2, hq = ch & 3;
        float2* Wb = (ch & 1) ? Ws1 : Ws0;
        float2* Wn = (ch & 1) ? Ws0 : Ws1;

        __syncthreads();     // prev MMA done with Wn buffer; Ap visible (ch=0)
        if (ch < 11) {
            const int nm = (ch + 1) >> 2, nh = (ch + 1) & 3;
#pragma unroll
            for (int t = 0; t < 8; t++) {
                int idx = tid + t * 256;
                int r = idx >> 4, q = idx & 15;
                cpa16(&Wn[r * 36 + 2 * q],
                      &g_Wh[(size_t)((nm * 512 + nh * 128 + r) << 5) + 2 * q]);
            }
            cp_commit();
            cp_wait<1>();
        } else {
            cp_wait<0>();
        }
        __syncthreads();     // W(ch) visible to all

        float c[2][4][4];
#pragma unroll
        for (int mt = 0; mt < 2; mt++)
#pragma unroll
            for (int nt = 0; nt < 4; nt++)
#pragma unroll
                for (int j = 0; j < 4; j++) c[mt][nt][j] = 0.0f;

#pragma unroll
        for (int s2 = 0; s2 < 8; s2++) {
            float2 A0  = Ap[(r0)      * 36 + 4 * s2 + tig];
            float2 A8  = Ap[(r0 + 8)  * 36 + 4 * s2 + tig];
            float2 A16 = Ap[(r0 + 16) * 36 + 4 * s2 + tig];
            float2 A24 = Ap[(r0 + 24) * 36 + 4 * s2 + tig];
#pragma unroll
            for (int nt = 0; nt < 4; nt++) {
                float2 Bv = Wb[(nw * 32 + nt * 8 + gid) * 36 + 4 * s2 + tig];
                mma_f16(c[0][nt], fu(A0.x),  fu(A8.x),  fu(A0.y),  fu(A8.y),  fu(Bv.x), fu(Bv.y));
                mma_f16(c[1][nt], fu(A16.x), fu(A24.x), fu(A16.y), fu(A24.y), fu(Bv.x), fu(Bv.y));
            }
        }

        if (mat < 2) {
            // ---- Q/K: nt-pairs pack into units directly ----
            float2* dst = (mat == 0) ? g_Qh : g_Kh;
#pragma unroll
            for (int mt = 0; mt < 2; mt++)
#pragma unroll
                for (int hf = 0; hf < 2; hf++) {
                    int rr = mw * 32 + mt * 16 + hf * 8 + gid;
                    int tok = m0 + rr, bbv = tok >> 9, srow = tok & 511;
                    size_t base = ((size_t)(bbv * NH_ + hq) * S_ + srow) * 32;
#pragma unroll
                    for (int p = 0; p < 2; p++) {
                        float2 v;
                        v.x = uf(h2u(c[mt][2 * p][hf * 2],     c[mt][2 * p][hf * 2 + 1]));
                        v.y = uf(h2u(c[mt][2 * p + 1][hf * 2], c[mt][2 * p + 1][hf * 2 + 1]));
                        dst[base + 8 * nw + 4 * p + tig] = v;
                    }
                }
        } else {
            // ---- V: stage in smem, transpose+repack to g_Vth [bh][d][kt4][32u] ----
            __syncthreads();
#pragma unroll
            for (int mt = 0; mt < 2; mt++)
#pragma unroll
                for (int hf = 0; hf < 2; hf++) {
                    int rr = mw * 32 + mt * 16 + hf * 8 + gid;
#pragma unroll
                    for (int nt = 0; nt < 4; nt++) {
                        int jd = 16 * nw + 4 * nt + tig;
                        *(__half2*)&Vst[rr * 132 + 2 * jd] =
                            __floats2half2_rn(c[mt][nt][hf * 2], c[mt][nt][hf * 2 + 1]);
                    }
                }
            __syncthreads();
            const int bbv = m0 >> 9;
            const int kt4 = (m0 & 511) >> 7;          // 128-kv tile index
            const int hi  = (m0 >> 6) & 1;            // which 64-half of the tile
            size_t vbase = (size_t)(bbv * NH_ + hq) * H_;
#pragma unroll
            for (int t = 0; t < 8; t++) {
                int idx = tid + t * 256;
                int d = idx >> 4, ul = idx & 15;
                int j0l = 8 * (ul >> 2) + (ul & 3);   // local kv-half2 index
                float2 o;
                o.x = uf(hh2u(Vst[(2 * j0l)     * 132 + d], Vst[(2 * j0l + 1) * 132 + d]));
                o.y = uf(hh2u(Vst[(2 * j0l + 8) * 132 + d], Vst[(2 * j0l + 9) * 132 + d]));
                g_Vth[((vbase + d) * 4 + kt4) * 32 + 16 * hi + ul] = o;
            }
        }
    }
}

// =============================================================================
// Kernel 2: flash attention, fp16 MMA, K-TILE 128 (4 iterations), cp.async fills.
// grid = (8 q-tiles, NH, B), 8 warps 4m x 2n (warp: m16 x n64 of the 64x128 S).
// smem 111616 B: Qh 64x36u, Kh 128x36u, Vth 128x36u, Ps 64x36u, rmax/rsum.
// =============================================================================
__global__ void __launch_bounds__(256, 2) attn_kernel(const int* __restrict__ mask)
{
    extern __shared__ float sm[];
    float2* Qh   = (float2*)sm;              // [0,4608)
    float2* Kh   = (float2*)(sm + 4608);     // [4608,13824)
    float2* Vth  = (float2*)(sm + 13824);    // [13824,23040)
    float2* Ps   = (float2*)(sm + 23040);    // [23040,27648)
    float*  rmax = sm + 27648;               // [2][64]
    float*  rsum = sm + 27776;               // [2][64] -> end 27904 floats

    const int tid = threadIdx.x, lane = tid & 31, wid = tid >> 5;
    const int gid = lane >> 2, tig = lane & 3;
    const int mw = wid & 3, nw = wid >> 2;
    const int q0 = blockIdx.x * 64;
    const int hq = blockIdx.y, bb = blockIdx.z;
    const int bh = bb * NH_ + hq;
    const int r0 = mw * 16 + gid;

    // Q tile fill (plain LDG, one-time)
#pragma unroll
    for (int t = 0; t < 4; t++) {
        int idx = tid + t * 256;
        int r = idx >> 4, q = idx & 15;
        float4 v = *(const float4*)&g_Qh[((size_t)bh * S_ + q0 + r) * 32 + 2 * q];
        *(float4*)&Qh[r * 36 + 2 * q] = v;
    }

    float O[8][4];
#pragma unroll
    for (int nt = 0; nt < 8; nt++)
#pragma unroll
        for (int j = 0; j < 4; j++) O[nt][j] = 0.0f;
    float m0v = -1e30f, m1v = -1e30f, l0 = 0.0f, l1 = 0.0f;

    for (int kt = 0; kt < 4; kt++) {
        __syncthreads();                     // prev PV done: Kh/Vth/Ps writable; Qh visible
        const int k0 = kt * 128;
        // K tile: 128 rows x 32u ; V tile: 128 d-rows x 32u  (cp.async)
#pragma unroll
        for (int t = 0; t < 8; t++) {
            int idx = tid + t * 256;
            int r = idx >> 4, q = idx & 15;
            cpa16(&Kh[r * 36 + 2 * q], &g_Kh[((size_t)bh * S_ + k0 + r) * 32 + 2 * q]);
        }
#pragma unroll
        for (int t = 0; t < 8; t++) {
            int idx = tid + t * 256;
            int d = idx >> 4, q = idx & 15;
            cpa16(&Vth[d * 36 + 2 * q], &g_Vth[(((size_t)bh * H_ + d) * 4 + kt) * 32 + 2 * q]);
        }
        cp_commit();
        cp_wait<0>();
        __syncthreads();                     // tile visible

        // ---- S = Q K^T  (64 x 128 per CTA; m16 x n64 per warp) ----
        float c[8][4];
#pragma unroll
        for (int nt = 0; nt < 8; nt++)
#pragma unroll
            for (int j = 0; j < 4; j++) c[nt][j] = 0.0f;
#pragma unroll
        for (int s2 = 0; s2 < 8; s2++) {
            float2 A0 = Qh[(r0)     * 36 + 4 * s2 + tig];
            float2 A8 = Qh[(r0 + 8) * 36 + 4 * s2 + tig];
#pragma unroll
            for (int nt = 0; nt < 8; nt++) {
                float2 Bv = Kh[(nw * 64 + nt * 8 + gid) * 36 + 4 * s2 + tig];
                mma_f16(c[nt], fu(A0.x), fu(A8.x), fu(A0.y), fu(A8.y), fu(Bv.x), fu(Bv.y));
            }
        }

        // ---- mask + row max ----
        float mx0 = -1e30f, mx1 = -1e30f;
#pragma unroll
        for (int nt = 0; nt < 8; nt++) {
            int kc = k0 + nw * 64 + nt * 8 + 2 * tig;
            int2 mk0 = *(const int2*)&mask[((size_t)bb * S_ + (q0 + r0)) * S_ + kc];
            int2 mk1 = *(const int2*)&mask[((size_t)bb * S_ + (q0 + r0 + 8)) * S_ + kc];
            if (mk0.x == 0) c[nt][0] = NEG_INF_;
            if (mk0.y == 0) c[nt][1] = NEG_INF_;
            if (mk1.x == 0) c[nt][2] = NEG_INF_;
            if (mk1.y == 0) c[nt][3] = NEG_INF_;
            mx0 = fmaxf(mx0, fmaxf(c[nt][0], c[nt][1]));
            mx1 = fmaxf(mx1, fmaxf(c[nt][2], c[nt][3]));
        }
        mx0 = fmaxf(mx0, __shfl_xor_sync(0xffffffffu, mx0, 1));
        mx0 = fmaxf(mx0, __shfl_xor_sync(0xffffffffu, mx0, 2));
        mx1 = fmaxf(mx1, __shfl_xor_sync(0xffffffffu, mx1, 1));
        mx1 = fmaxf(mx1, __shfl_xor_sync(0xffffffffu, mx1, 2));
        if (tig == 0) {
            rmax[nw * 64 + r0]     = mx0;
            rmax[nw * 64 + r0 + 8] = mx1;
        }
        __syncthreads();

        float nm0 = fmaxf(m0v, fmaxf(rmax[r0],     rmax[64 + r0]));
        float nm1 = fmaxf(m1v, fmaxf(rmax[r0 + 8], rmax[64 + r0 + 8]));
        float al0 = __expf(m0v - nm0), al1 = __expf(m1v - nm1);
        m0v = nm0; m1v = nm1;

        float s0 = 0.0f, s1 = 0.0f;
#pragma unroll
        for (int p = 0; p < 4; p++) {
            float e00 = __expf(c[2 * p][0] - nm0),     e01 = __expf(c[2 * p][1] - nm0);
            float e10 = __expf(c[2 * p + 1][0] - nm0), e11 = __expf(c[2 * p + 1][1] - nm0);
            float f00 = __expf(c[2 * p][2] - nm1),     f01 = __expf(c[2 * p][3] - nm1);
            float f10 = __expf(c[2 * p + 1][2] - nm1), f11 = __expf(c[2 * p + 1][3] - nm1);
            s0 += e00 + e01 + e10 + e11;
            s1 += f00 + f01 + f10 + f11;
            float2 v0, v1;
            v0.x = uf(h2u(e00, e01)); v0.y = uf(h2u(e10, e11));
            v1.x = uf(h2u(f00, f01)); v1.y = uf(h2u(f10, f11));
            Ps[(r0)     * 36 + 16 * nw + 4 * p + tig] = v0;
            Ps[(r0 + 8) * 36 + 16 * nw + 4 * p + tig] = v1;
        }
        s0 += __shfl_xor_sync(0xffffffffu, s0, 1);
        s0 += __shfl_xor_sync(0xffffffffu, s0, 2);
        s1 += __shfl_xor_sync(0xffffffffu, s1, 1);
        s1 += __shfl_xor_sync(0xffffffffu, s1, 2);
        if (tig == 0) {
            rsum[nw * 64 + r0]     = s0;
            rsum[nw * 64 + r0 + 8] = s1;
        }
#pragma unroll
        for (int nt = 0; nt < 8; nt++) {
            O[nt][0] *= al0; O[nt][1] *= al0;
            O[nt][2] *= al1; O[nt][3] *= al1;
        }
        __syncthreads();                     // Ps + rsum visible

        l0 = l0 * al0 + rsum[r0]     + rsum[64 + r0];
        l1 = l1 * al1 + rsum[r0 + 8] + rsum[64 + r0 + 8];

        // ---- O += P @ V  (k = 128 kv) ----
#pragma unroll
        for (int s2v = 0; s2v < 8; s2v++) {
            float2 A0 = Ps[(r0)     * 36 + 4 * s2v + tig];
            float2 A8 = Ps[(r0 + 8) * 36 + 4 * s2v + tig];
#pragma unroll
            for (int nt = 0; nt < 8; nt++) {
                float2 Bv = Vth[(nw * 64 + nt * 8 + gid) * 36 + 4 * s2v + tig];
                mma_f16(O[nt], fu(A0.x), fu(A8.x), fu(A0.y), fu(A8.y), fu(Bv.x), fu(Bv.y));
            }
        }
    }

    // ---- normalize, pack ctx units ----
    float inv0 = 1.0f / l0, inv1 = 1.0f / l1;
    size_t cb0 = ((size_t)(bb * S_ + q0 + r0)     * 4 + hq) * 32;
    size_t cb1 = ((size_t)(bb * S_ + q0 + r0 + 8) * 4 + hq) * 32;
#pragma unroll
    for (int p = 0; p < 4; p++) {
        float2 v0, v1;
        v0.x = uf(h2u(O[2 * p][0] * inv0,     O[2 * p][1] * inv0));
        v0.y = uf(h2u(O[2 * p + 1][0] * inv0, O[2 * p + 1][1] * inv0));
        v1.x = uf(h2u(O[2 * p][2] * inv1,     O[2 * p][3] * inv1));
        v1.y = uf(h2u(O[2 * p + 1][2] * inv1, O[2 * p + 1][3] * inv1));
        g_ctxh[cb0 + 16 * nw + 4 * p + tig] = v0;
        g_ctxh[cb1 + 16 * nw + 4 * p + tig] = v1;
    }
}

// =============================================================================
// Kernel 3: out = ctx @ Wo + enc, LayerNorm.  fp16 MMA, DOUBLE-BUFFERED chunks.
// CTA = 64 tokens x N=128; 8 warps (2m x 4n).  smem 110592 B.
// =============================================================================
__global__ void __launch_bounds__(256, 2) out_kernel(
    const float* __restrict__ enc, const float* __restrict__ gamma,
    const float* __restrict__ beta, float* __restrict__ out)
{
    extern __shared__ float sm[];
    float2* Ap0 = (float2*)sm;               // [0,4608)
    float2* Ap1 = (float2*)(sm + 4608);      // [4608,9216)
    float2* Ws0 = (float2*)(sm + 9216);      // [9216,18432)
    float2* Ws1 = (float2*)(sm + 18432);     // [18432,27648)
    float*  Cs  = sm;                        // alias: 64x132 floats (8448 < 9216)

    const int tid = threadIdx.x, lane = tid & 31, wid = tid >> 5;
    const int gid = lane >> 2, tig = lane & 3;
    const int mw = wid & 1, nw = wid >> 1;
    const int m0 = blockIdx.x * 64;
    const int r0 = mw * 32 + gid;

    // prefetch chunk 0
#pragma unroll
    for (int t = 0; t < 4; t++) {
        int idx = tid + t * 256;
        int r = idx >> 4, q = idx & 15;
        cpa16(&Ap0[r * 36 + 2 * q], &g_ctxh[((size_t)(m0 + r) * 4) * 32 + 2 * q]);
    }
#pragma unroll
    for (int t = 0; t < 8; t++) {
        int idx = tid + t * 256;
        int r = idx >> 4, q = idx & 15;
        cpa16(&Ws0[r * 36 + 2 * q], &g_Woh[((size_t)r * 4) * 32 + 2 * q]);
    }
    cp_commit();

    float c[2][4][4];
#pragma unroll
    for (int mt = 0; mt < 2; mt++)
#pragma unroll
        for (int nt = 0; nt < 4; nt++)
#pragma unroll
            for (int j = 0; j < 4; j++) c[mt][nt][j] = 0.0f;

    for (int kc = 0; kc < 4; kc++) {
        float2* Ab = (kc & 1) ? Ap1 : Ap0;
        float2* Wb = (kc & 1) ? Ws1 : Ws0;
        float2* An = (kc & 1) ? Ap0 : Ap1;
        float2* Wn = (kc & 1) ? Ws0 : Ws1;

        __syncthreads();                     // prev MMA done with An/Wn
        if (kc < 3) {
#pragma unroll
            for (int t = 0; t < 4; t++) {
                int idx = tid + t * 256;
                int r = idx >> 4, q = idx & 15;
                cpa16(&An[r * 36 + 2 * q],
                      &g_ctxh[((size_t)(m0 + r) * 4 + kc + 1) * 32 + 2 * q]);
            }
#pragma unroll
            for (int t = 0; t < 8; t++) {
                int idx = tid + t * 256;
                int r = idx >> 4, q = idx & 15;
                cpa16(&Wn[r * 36 + 2 * q],
                      &g_Woh[((size_t)r * 4 + kc + 1) * 32 + 2 * q]);
            }
            cp_commit();
            cp_wait<1>();
        } else {
            cp_wait<0>();
        }
        __syncthreads();                     // chunk kc visible

#pragma unroll
        for (int s2 = 0; s2 < 8; s2++) {
            float2 A0  = Ab[(r0)      * 36 + 4 * s2 + tig];
            float2 A8  = Ab[(r0 + 8)  * 36 + 4 * s2 + tig];
            float2 A16 = Ab[(r0 + 16) * 36 + 4 * s2 + tig];
            float2 A24 = Ab[(r0 + 24) * 36 + 4 * s2 + tig];
#pragma unroll
            for (int nt = 0; nt < 4; nt++) {
                float2 Bv = Wb[(nw * 32 + nt * 8 + gid) * 36 + 4 * s2 + tig];
                mma_f16(c[0][nt], fu(A0.x),  fu(A8.x),  fu(A0.y),  fu(A8.y),  fu(Bv.x), fu(Bv.y));
                mma_f16(c[1][nt], fu(A16.x), fu(A24.x), fu(A16.y), fu(A24.y), fu(Bv.x), fu(Bv.y));
            }
        }
    }
    __syncthreads();                         // done with buffers -> reuse as Cs

#pragma unroll
    for (int mt = 0; mt < 2; mt++)
#pragma unroll
        for (int hf = 0; hf < 2; hf++) {
            int rr = mw * 32 + mt * 16 + hf * 8 + gid;
#pragma unroll
            for (int nt = 0; nt < 4; nt++) {
                int col = nw * 32 + nt * 8 + 2 * tig;
                *(float2*)&Cs[rr * 132 + col] =
                    make_float2(c[mt][nt][hf * 2 + 0], c[mt][nt][hf * 2 + 1]);
            }
        }
    __syncthreads();

    // ---- LayerNorm: 4 threads per row, 32 cols each ----
    const int row = tid >> 2, q = tid & 3;
    float x[32];
    float ssum = 0.0f, ssq = 0.0f;
#pragma unroll
    for (int i = 0; i < 8; i++) {
        float4 v = *(float4*)&Cs[row * 132 + q * 32 + i * 4];
        float4 e = *(const float4*)&enc[(size_t)(m0 + row) * H_ + q * 32 + i * 4];
        x[4 * i + 0] = v.x + e.x; x[4 * i + 1] = v.y + e.y;
        x[4 * i + 2] = v.z + e.z; x[4 * i + 3] = v.w + e.w;
#pragma unroll
        for (int j = 0; j < 4; j++) {
            ssum += x[4 * i + j];
            ssq  += x[4 * i + j] * x[4 * i + j];
        }
    }
    ssum += __shfl_xor_sync(0xffffffffu, ssum, 1);
    ssum += __shfl_xor_sync(0xffffffffu, ssum, 2);
    ssq  += __shfl_xor_sync(0xffffffffu, ssq,  1);
    ssq  += __shfl_xor_sync(0xffffffffu, ssq,  2);
    float mean = ssum * (1.0f / 128.0f);
    float var  = ssq * (1.0f / 128.0f) - mean * mean;
    float rstd = rsqrtf(var + 1e-6f);

#pragma unroll
    for (int i = 0; i < 8; i++) {
        float4 g  = *(const float4*)&gamma[q * 32 + i * 4];
        float4 be = *(const float4*)&beta[q * 32 + i * 4];
        float4 y = make_float4((x[4 * i + 0] - mean) * rstd * g.x + be.x,
                               (x[4 * i + 1] - mean) * rstd * g.y + be.y,
                               (x[4 * i + 2] - mean) * rstd * g.z + be.z,
                               (x[4 * i + 3] - mean) * rstd * g.w + be.w);
        *(float4*)&out[(size_t)(m0 + row) * H_ + q * 32 + i * 4] = y;
    }
}

// =============================================================================
extern "C" void kernel_launch(void* const* d_in, const int* in_sizes, int n_in,
                              void* d_out, int out_size)
{
    const float* enc   = (const float*)d_in[0];
    const int*   mask  = (const int*)  d_in[1];
    const float* Wq    = (const float*)d_in[2];
    const float* Wk    = (const float*)d_in[3];
    const float* Wv    = (const float*)d_in[4];
    const float* Wo    = (const float*)d_in[5];
    const float* gamma = (const float*)d_in[6];
    const float* beta  = (const float*)d_in[7];
    float* out = (float*)d_out;

    prep_kernel<<<256, 256>>>(Wq, Wk, Wv, Wo);

    const int smem1 = 109056;
    cudaFuncSetAttribute(qkv_kernel, cudaFuncAttributeMaxDynamicSharedMemorySize, smem1);
    qkv_kernel<<<(B_ * S_) / 64, 256, smem1>>>(enc);

    const int smem2 = 111616;
    cudaFuncSetAttribute(attn_kernel, cudaFuncAttributeMaxDynamicSharedMemorySize, smem2);
    dim3 g2(S_ / 64, NH_, B_);
    attn_kernel<<<g2, 256, smem2>>>(mask);

    const int smem3 = 110592;
    cudaFuncSetAttribute(out_kernel, cudaFuncAttributeMaxDynamicSharedMemorySize, smem3);
    out_kernel<<<(B_ * S_) / 64, 256, smem3>>>(enc, gamma, beta, out);
}

// round 10
// speedup vs baseline: 2.4640x; 1.0595x over previous
#include <cuda_runtime.h>
#include <cuda_fp16.h>

#define B_    64
#define S_    512
#define H_    128
#define NH_   4
#define NHH_  512
#define QSCALE 0.08838834764831845f   /* 1/sqrt(128) */
#define NEG_INF_ -1e9f

// ---------------- packed fp16 scratch ----------------------------------------
// "Unit" = float2 (8B) = 2 half2: unit u holds (h2[j], h2[j+4]) with
// j = 8*(u>>2) + (u&3).  h2[j] = (T[2j], T[2j+1]) along the MMA k-dim.
__device__ float2 g_Qh [(size_t)B_ * NH_ * S_ * 32];      // [bh][s][32u]  (k=d 128)
__device__ float2 g_Kh [(size_t)B_ * NH_ * S_ * 32];      // [bh][s][32u]
__device__ float2 g_Vth[(size_t)B_ * NH_ * H_ * 4 * 32];  // [bh][d][kt4][32u] (k=kv 128/tile)
__device__ float2 g_ctxh[(size_t)B_ * S_ * 4 * 32];       // [tok][kc4][32u]
__device__ float2 g_Wh [3 * 512 * 32];                    // [mat][n][32u], Wq*QSCALE folded
__device__ float2 g_Woh[128 * 4 * 32];                    // [n][kc4][32u]

// ---------------- helpers ----------------------------------------------------
__device__ __forceinline__ unsigned h2u(float x, float y) {
    __half2 h = __floats2half2_rn(x, y);
    return *reinterpret_cast<unsigned*>(&h);
}
__device__ __forceinline__ unsigned hh2u(__half x, __half y) {
    __half2 h = __halves2half2(x, y);
    return *reinterpret_cast<unsigned*>(&h);
}
__device__ __forceinline__ unsigned fu(float x) { return __float_as_uint(x); }
__device__ __forceinline__ float    uf(unsigned u) { return __uint_as_float(u); }

__device__ __forceinline__ void mma_f16(float c[4],
                                        unsigned a0, unsigned a1, unsigned a2, unsigned a3,
                                        unsigned b0, unsigned b1) {
    asm volatile(
        "mma.sync.aligned.m16n8k16.row.col.f32.f16.f16.f32 "
        "{%0,%1,%2,%3}, {%4,%5,%6,%7}, {%8,%9}, {%0,%1,%2,%3};"
        : "+f"(c[0]), "+f"(c[1]), "+f"(c[2]), "+f"(c[3])
        : "r"(a0), "r"(a1), "r"(a2), "r"(a3), "r"(b0), "r"(b1));
}

__device__ __forceinline__ void cpa16(void* dst, const void* src) {
    unsigned d = (unsigned)__cvta_generic_to_shared(dst);
    asm volatile("cp.async.cg.shared.global [%0], [%1], 16;" :: "r"(d), "l"(src));
}
__device__ __forceinline__ void cp_commit() { asm volatile("cp.async.commit_group;"); }
template<int N> __device__ __forceinline__ void cp_wait() {
    asm volatile("cp.async.wait_group %0;" :: "n"(N));
}

// =============================================================================
// Kernel 0: pack weights to fp16 packed-unit layout. 65536 threads.
// =============================================================================
__global__ void __launch_bounds__(256) prep_kernel(
    const float* __restrict__ Wq, const float* __restrict__ Wk,
    const float* __restrict__ Wv, const float* __restrict__ Wo)
{
    int idx = blockIdx.x * 256 + threadIdx.x;
    if (idx < 3 * 512 * 32) {
        int u = idx & 31, n = (idx >> 5) & 511, mat = idx >> 14;
        const float* W = (mat == 0) ? Wq : (mat == 1) ? Wk : Wv;
        float scl = (mat == 0) ? QSCALE : 1.0f;
        int j = 8 * (u >> 2) + (u & 3);
        float2 v;
        v.x = uf(h2u(W[(size_t)(2 * j)     * NHH_ + n] * scl,
                     W[(size_t)(2 * j + 1) * NHH_ + n] * scl));
        v.y = uf(h2u(W[(size_t)(2 * j + 8) * NHH_ + n] * scl,
                     W[(size_t)(2 * j + 9) * NHH_ + n] * scl));
        g_Wh[idx] = v;
    } else {
        int i2 = idx - 3 * 512 * 32;
        int u = i2 & 31, kc = (i2 >> 5) & 3, n = i2 >> 7;
        int j = 8 * (u >> 2) + (u & 3);
        int kb = kc * 128;
        float2 v;
        v.x = uf(h2u(Wo[(size_t)(kb + 2 * j)     * H_ + n],
                     Wo[(size_t)(kb + 2 * j + 1) * H_ + n]));
        v.y = uf(h2u(Wo[(size_t)(kb + 2 * j + 8) * H_ + n],
                     Wo[(size_t)(kb + 2 * j + 9) * H_ + n]));
        g_Woh[(size_t)(n * 4 + kc) * 32 + u] = v;
    }
}

// =============================================================================
// Kernel 1: QKV projection, m-resident, fp16 MMA, DOUBLE-BUFFERED W prefetch.
// (unchanged from R8/R9 — verified)
// =============================================================================
__global__ void __launch_bounds__(256, 2) qkv_kernel(const float* __restrict__ enc)
{
    extern __shared__ float sm[];
    float2* Ap  = (float2*)sm;              // [0,4608)
    float2* Ws0 = (float2*)(sm + 4608);     // [4608,13824)
    float2* Ws1 = (float2*)(sm + 13824);    // [13824,23040)
    __half* Vst = (__half*)(sm + 23040);    // 64x132 halfs (16896 B)

    const int tid = threadIdx.x, lane = tid & 31, wid = tid >> 5;
    const int gid = lane >> 2, tig = lane & 3;
    const int mw = wid & 1, nw = wid >> 1;
    const int m0 = blockIdx.x * 64;
    const int r0 = mw * 32 + gid;
    __half2* Aph2 = (__half2*)Ap;

#pragma unroll
    for (int t = 0; t < 8; t++) {
        int idx = tid + t * 256;
        int r = idx >> 5, sl = idx & 31;
        float4 a = *(const float4*)&enc[(size_t)(m0 + r) * H_ + sl * 4];
        int j0 = 2 * sl, j1 = 2 * sl + 1;
        int u0 = 4 * (j0 >> 3) + (j0 & 3), c0 = (j0 >> 2) & 1;
        int u1 = 4 * (j1 >> 3) + (j1 & 3), c1 = (j1 >> 2) & 1;
        Aph2[(r * 36 + u0) * 2 + c0] = __floats2half2_rn(a.x, a.y);
        Aph2[(r * 36 + u1) * 2 + c1] = __floats2half2_rn(a.z, a.w);
    }

#pragma unroll
    for (int t = 0; t < 8; t++) {
        int idx = tid + t * 256;
        int r = idx >> 4, q = idx & 15;
        cpa16(&Ws0[r * 36 + 2 * q], &g_Wh[(size_t)(r << 5) + 2 * q]);
    }
    cp_commit();

    for (int ch = 0; ch < 12; ch++) {
        const int mat = ch >> 2, hq = ch & 3;
        float2* Wb = (ch & 1) ? Ws1 : Ws0;
        float2* Wn = (ch & 1) ? Ws0 : Ws1;

        __syncthreads();
        if (ch < 11) {
            const int nm = (ch + 1) >> 2, nh = (ch + 1) & 3;
#pragma unroll
            for (int t = 0; t < 8; t++) {
                int idx = tid + t * 256;
                int r = idx >> 4, q = idx & 15;
                cpa16(&Wn[r * 36 + 2 * q],
                      &g_Wh[(size_t)((nm * 512 + nh * 128 + r) << 5) + 2 * q]);
            }
            cp_commit();
            cp_wait<1>();
        } else {
            cp_wait<0>();
        }
        __syncthreads();

        float c[2][4][4];
#pragma unroll
        for (int mt = 0; mt < 2; mt++)
#pragma unroll
            for (int nt = 0; nt < 4; nt++)
#pragma unroll
                for (int j = 0; j < 4; j++) c[mt][nt][j] = 0.0f;

#pragma unroll
        for (int s2 = 0; s2 < 8; s2++) {
            float2 A0  = Ap[(r0)      * 36 + 4 * s2 + tig];
            float2 A8  = Ap[(r0 + 8)  * 36 + 4 * s2 + tig];
            float2 A16 = Ap[(r0 + 16) * 36 + 4 * s2 + tig];
            float2 A24 = Ap[(r0 + 24) * 36 + 4 * s2 + tig];
#pragma unroll
            for (int nt = 0; nt < 4; nt++) {
                float2 Bv = Wb[(nw * 32 + nt * 8 + gid) * 36 + 4 * s2 + tig];
                mma_f16(c[0][nt], fu(A0.x),  fu(A8.x),  fu(A0.y),  fu(A8.y),  fu(Bv.x), fu(Bv.y));
                mma_f16(c[1][nt], fu(A16.x), fu(A24.x), fu(A16.y), fu(A24.y), fu(Bv.x), fu(Bv.y));
            }
        }

        if (mat < 2) {
            float2* dst = (mat == 0) ? g_Qh : g_Kh;
#pragma unroll
            for (int mt = 0; mt < 2; mt++)
#pragma unroll
                for (int hf = 0; hf < 2; hf++) {
                    int rr = mw * 32 + mt * 16 + hf * 8 + gid;
                    int tok = m0 + rr, bbv = tok >> 9, srow = tok & 511;
                    size_t base = ((size_t)(bbv * NH_ + hq) * S_ + srow) * 32;
#pragma unroll
                    for (int p = 0; p < 2; p++) {
                        float2 v;
                        v.x = uf(h2u(c[mt][2 * p][hf * 2],     c[mt][2 * p][hf * 2 + 1]));
                        v.y = uf(h2u(c[mt][2 * p + 1][hf * 2], c[mt][2 * p + 1][hf * 2 + 1]));
                        dst[base + 8 * nw + 4 * p + tig] = v;
                    }
                }
        } else {
            __syncthreads();
#pragma unroll
            for (int mt = 0; mt < 2; mt++)
#pragma unroll
                for (int hf = 0; hf < 2; hf++) {
                    int rr = mw * 32 + mt * 16 + hf * 8 + gid;
#pragma unroll
                    for (int nt = 0; nt < 4; nt++) {
                        int jd = 16 * nw + 4 * nt + tig;
                        *(__half2*)&Vst[rr * 132 + 2 * jd] =
                            __floats2half2_rn(c[mt][nt][hf * 2], c[mt][nt][hf * 2 + 1]);
                    }
                }
            __syncthreads();
            const int bbv = m0 >> 9;
            const int kt4 = (m0 & 511) >> 7;
            const int hi  = (m0 >> 6) & 1;
            size_t vbase = (size_t)(bbv * NH_ + hq) * H_;
#pragma unroll
            for (int t = 0; t < 8; t++) {
                int idx = tid + t * 256;
                int d = idx >> 4, ul = idx & 15;
                int j0l = 8 * (ul >> 2) + (ul & 3);
                float2 o;
                o.x = uf(hh2u(Vst[(2 * j0l)     * 132 + d], Vst[(2 * j0l + 1) * 132 + d]));
                o.y = uf(hh2u(Vst[(2 * j0l + 8) * 132 + d], Vst[(2 * j0l + 9) * 132 + d]));
                g_Vth[((vbase + d) * 4 + kt4) * 32 + 16 * hi + ul] = o;
            }
        }
    }
}

// =============================================================================
// Kernel 2: FA2-style flash attention.  Q-TILE 128, 8 warps; each warp owns 16
// q-rows x full 128-k width -> softmax is warp-local (quad shuffles only), P
// stays in registers (c-frags ARE the PV a-frags).  2 barriers per k-iter.
// K/V double-buffered cp.async.  smem 184320 B, 1 CTA/SM, grid (4, NH, B).
// =============================================================================
__global__ void __launch_bounds__(256, 1) attn_kernel(const int* __restrict__ mask)
{
    extern __shared__ float sm[];
    float2* Qh  = (float2*)sm;               // 128x36u  floats [0,9216)
    float2* Kb0 = (float2*)(sm + 9216);      // [9216,18432)
    float2* Kb1 = (float2*)(sm + 18432);     // [18432,27648)
    float2* Vb0 = (float2*)(sm + 27648);     // [27648,36864)
    float2* Vb1 = (float2*)(sm + 36864);     // [36864,46080)

    const int tid = threadIdx.x, lane = tid & 31, wq = tid >> 5;
    const int gid = lane >> 2, tig = lane & 3;
    const int q0 = blockIdx.x * 128;
    const int hq = blockIdx.y, bb = blockIdx.z;
    const int bh = bb * NH_ + hq;
    const int r0 = wq * 16 + gid;            // this thread's first q-row (local)
    const int gq0 = q0 + r0, gq1 = gq0 + 8;

    // prefetch Q (128 rows) + K/V tile 0 as one group
#pragma unroll
    for (int t = 0; t < 8; t++) {
        int idx = tid + t * 256;
        int r = idx >> 4, q = idx & 15;
        cpa16(&Qh[r * 36 + 2 * q], &g_Qh[((size_t)bh * S_ + q0 + r) * 32 + 2 * q]);
    }
#pragma unroll
    for (int t = 0; t < 8; t++) {
        int idx = tid + t * 256;
        int r = idx >> 4, q = idx & 15;
        cpa16(&Kb0[r * 36 + 2 * q], &g_Kh[((size_t)bh * S_ + r) * 32 + 2 * q]);
    }
#pragma unroll
    for (int t = 0; t < 8; t++) {
        int idx = tid + t * 256;
        int d = idx >> 4, q = idx & 15;
        cpa16(&Vb0[d * 36 + 2 * q], &g_Vth[(((size_t)bh * H_ + d) * 4) * 32 + 2 * q]);
    }
    cp_commit();

    float O[16][4];
#pragma unroll
    for (int nt = 0; nt < 16; nt++)
#pragma unroll
        for (int j = 0; j < 4; j++) O[nt][j] = 0.0f;
    float m0v = -1e30f, m1v = -1e30f, l0 = 0.0f, l1 = 0.0f;

    for (int kt = 0; kt < 4; kt++) {
        float2* Kc = (kt & 1) ? Kb1 : Kb0;
        float2* Vc = (kt & 1) ? Vb1 : Vb0;
        float2* Kn = (kt & 1) ? Kb0 : Kb1;
        float2* Vn = (kt & 1) ? Vb0 : Vb1;
        const int k0 = kt * 128;

        __syncthreads();                     // all warps done reading Kn/Vn (iter kt-1)
        if (kt < 3) {
#pragma unroll
            for (int t = 0; t < 8; t++) {
                int idx = tid + t * 256;
                int r = idx >> 4, q = idx & 15;
                cpa16(&Kn[r * 36 + 2 * q],
                      &g_Kh[((size_t)bh * S_ + k0 + 128 + r) * 32 + 2 * q]);
            }
#pragma unroll
            for (int t = 0; t < 8; t++) {
                int idx = tid + t * 256;
                int d = idx >> 4, q = idx & 15;
                cpa16(&Vn[d * 36 + 2 * q],
                      &g_Vth[(((size_t)bh * H_ + d) * 4 + kt + 1) * 32 + 2 * q]);
            }
            cp_commit();
            cp_wait<1>();                    // tile kt complete (kt+1 may be pending)
        } else {
            cp_wait<0>();
        }
        __syncthreads();                     // tile kt visible to all

        // ---- S = Q K^T : 16 q-rows x 128 k-cols per warp ----
        float c[16][4];
#pragma unroll
        for (int nt = 0; nt < 16; nt++)
#pragma unroll
            for (int j = 0; j < 4; j++) c[nt][j] = 0.0f;
#pragma unroll
        for (int s2 = 0; s2 < 8; s2++) {
            float2 A0 = Qh[(r0)     * 36 + 4 * s2 + tig];
            float2 A8 = Qh[(r0 + 8) * 36 + 4 * s2 + tig];
#pragma unroll
            for (int nt = 0; nt < 16; nt++) {
                float2 Bv = Kc[(8 * nt + gid) * 36 + 4 * s2 + tig];
                mma_f16(c[nt], fu(A0.x), fu(A8.x), fu(A0.y), fu(A8.y), fu(Bv.x), fu(Bv.y));
            }
        }

        // ---- mask + row max (warp-local: full row in this warp) ----
        float mx0 = -1e30f, mx1 = -1e30f;
#pragma unroll
        for (int nt = 0; nt < 16; nt++) {
            int kc = k0 + 8 * nt + 2 * tig;
            int2 mk0 = *(const int2*)&mask[((size_t)bb * S_ + gq0) * S_ + kc];
            int2 mk1 = *(const int2*)&mask[((size_t)bb * S_ + gq1) * S_ + kc];
            if (mk0.x == 0) c[nt][0] = NEG_INF_;
            if (mk0.y == 0) c[nt][1] = NEG_INF_;
            if (mk1.x == 0) c[nt][2] = NEG_INF_;
            if (mk1.y == 0) c[nt][3] = NEG_INF_;
            mx0 = fmaxf(mx0, fmaxf(c[nt][0], c[nt][1]));
            mx1 = fmaxf(mx1, fmaxf(c[nt][2], c[nt][3]));
        }
        mx0 = fmaxf(mx0, __shfl_xor_sync(0xffffffffu, mx0, 1));
        mx0 = fmaxf(mx0, __shfl_xor_sync(0xffffffffu, mx0, 2));
        mx1 = fmaxf(mx1, __shfl_xor_sync(0xffffffffu, mx1, 1));
        mx1 = fmaxf(mx1, __shfl_xor_sync(0xffffffffu, mx1, 2));

        float nm0 = fmaxf(m0v, mx0), nm1 = fmaxf(m1v, mx1);
        float al0 = __expf(m0v - nm0), al1 = __expf(m1v - nm1);
        m0v = nm0; m1v = nm1;

        // exp in-register (reuse c), accumulate row sums
        float s0 = 0.0f, s1 = 0.0f;
#pragma unroll
        for (int nt = 0; nt < 16; nt++) {
            c[nt][0] = __expf(c[nt][0] - nm0);
            c[nt][1] = __expf(c[nt][1] - nm0);
            c[nt][2] = __expf(c[nt][2] - nm1);
            c[nt][3] = __expf(c[nt][3] - nm1);
            s0 += c[nt][0] + c[nt][1];
            s1 += c[nt][2] + c[nt][3];
        }
        s0 += __shfl_xor_sync(0xffffffffu, s0, 1);
        s0 += __shfl_xor_sync(0xffffffffu, s0, 2);
        s1 += __shfl_xor_sync(0xffffffffu, s1, 1);
        s1 += __shfl_xor_sync(0xffffffffu, s1, 2);
        l0 = l0 * al0 + s0;
        l1 = l1 * al1 + s1;

#pragma unroll
        for (int nt = 0; nt < 16; nt++) {
            O[nt][0] *= al0; O[nt][1] *= al0;
            O[nt][2] *= al1; O[nt][3] *= al1;
        }

        // ---- O += P @ V : P packed from c-frags (c[2p],c[2p+1] = a-frag of k-step p) ----
#pragma unroll
        for (int p = 0; p < 8; p++) {
            unsigned pa0 = h2u(c[2 * p][0],     c[2 * p][1]);
            unsigned pa1 = h2u(c[2 * p][2],     c[2 * p][3]);
            unsigned pa2 = h2u(c[2 * p + 1][0], c[2 * p + 1][1]);
            unsigned pa3 = h2u(c[2 * p + 1][2], c[2 * p + 1][3]);
#pragma unroll
            for (int ntd = 0; ntd < 16; ntd++) {
                float2 Bv = Vc[(8 * ntd + gid) * 36 + 4 * p + tig];
                mma_f16(O[ntd], pa0, pa1, pa2, pa3, fu(Bv.x), fu(Bv.y));
            }
        }
    }

    // ---- normalize, pack ctx units (units 4p+tig cover 0..31) ----
    float inv0 = 1.0f / l0, inv1 = 1.0f / l1;
    size_t cb0 = ((size_t)(bb * S_ + gq0) * 4 + hq) * 32;
    size_t cb1 = ((size_t)(bb * S_ + gq1) * 4 + hq) * 32;
#pragma unroll
    for (int p = 0; p < 8; p++) {
        float2 v0, v1;
        v0.x = uf(h2u(O[2 * p][0] * inv0,     O[2 * p][1] * inv0));
        v0.y = uf(h2u(O[2 * p + 1][0] * inv0, O[2 * p + 1][1] * inv0));
        v1.x = uf(h2u(O[2 * p][2] * inv1,     O[2 * p][3] * inv1));
        v1.y = uf(h2u(O[2 * p + 1][2] * inv1, O[2 * p + 1][3] * inv1));
        g_ctxh[cb0 + 4 * p + tig] = v0;
        g_ctxh[cb1 + 4 * p + tig] = v1;
    }
}

// =============================================================================
// Kernel 3: out = ctx @ Wo + enc, LayerNorm.  (unchanged from R8/R9)
// =============================================================================
__global__ void __launch_bounds__(256, 2) out_kernel(
    const float* __restrict__ enc, const float* __restrict__ gamma,
    const float* __restrict__ beta, float* __restrict__ out)
{
    extern __shared__ float sm[];
    float2* Ap0 = (float2*)sm;
    float2* Ap1 = (float2*)(sm + 4608);
    float2* Ws0 = (float2*)(sm + 9216);
    float2* Ws1 = (float2*)(sm + 18432);
    float*  Cs  = sm;

    const int tid = threadIdx.x, lane = tid & 31, wid = tid >> 5;
    const int gid = lane >> 2, tig = lane & 3;
    const int mw = wid & 1, nw = wid >> 1;
    const int m0 = blockIdx.x * 64;
    const int r0 = mw * 32 + gid;

#pragma unroll
    for (int t = 0; t < 4; t++) {
        int idx = tid + t * 256;
        int r = idx >> 4, q = idx & 15;
        cpa16(&Ap0[r * 36 + 2 * q], &g_ctxh[((size_t)(m0 + r) * 4) * 32 + 2 * q]);
    }
#pragma unroll
    for (int t = 0; t < 8; t++) {
        int idx = tid + t * 256;
        int r = idx >> 4, q = idx & 15;
        cpa16(&Ws0[r * 36 + 2 * q], &g_Woh[((size_t)r * 4) * 32 + 2 * q]);
    }
    cp_commit();

    float c[2][4][4];
#pragma unroll
    for (int mt = 0; mt < 2; mt++)
#pragma unroll
        for (int nt = 0; nt < 4; nt++)
#pragma unroll
            for (int j = 0; j < 4; j++) c[mt][nt][j] = 0.0f;

    for (int kc = 0; kc < 4; kc++) {
        float2* Ab = (kc & 1) ? Ap1 : Ap0;
        float2* Wb = (kc & 1) ? Ws1 : Ws0;
        float2* An = (kc & 1) ? Ap0 : Ap1;
        float2* Wn = (kc & 1) ? Ws0 : Ws1;

        __syncthreads();
        if (kc < 3) {
#pragma unroll
            for (int t = 0; t < 4; t++) {
                int idx = tid + t * 256;
                int r = idx >> 4, q = idx & 15;
                cpa16(&An[r * 36 + 2 * q],
                      &g_ctxh[((size_t)(m0 + r) * 4 + kc + 1) * 32 + 2 * q]);
            }
#pragma unroll
            for (int t = 0; t < 8; t++) {
                int idx = tid + t * 256;
                int r = idx >> 4, q = idx & 15;
                cpa16(&Wn[r * 36 + 2 * q],
                      &g_Woh[((size_t)r * 4 + kc + 1) * 32 + 2 * q]);
            }
            cp_commit();
            cp_wait<1>();
        } else {
            cp_wait<0>();
        }
        __syncthreads();

#pragma unroll
        for (int s2 = 0; s2 < 8; s2++) {
            float2 A0  = Ab[(r0)      * 36 + 4 * s2 + tig];
            float2 A8  = Ab[(r0 + 8)  * 36 + 4 * s2 + tig];
            float2 A16 = Ab[(r0 + 16) * 36 + 4 * s2 + tig];
            float2 A24 = Ab[(r0 + 24) * 36 + 4 * s2 + tig];
#pragma unroll
            for (int nt = 0; nt < 4; nt++) {
                float2 Bv = Wb[(nw * 32 + nt * 8 + gid) * 36 + 4 * s2 + tig];
                mma_f16(c[0][nt], fu(A0.x),  fu(A8.x),  fu(A0.y),  fu(A8.y),  fu(Bv.x), fu(Bv.y));
                mma_f16(c[1][nt], fu(A16.x), fu(A24.x), fu(A16.y), fu(A24.y), fu(Bv.x), fu(Bv.y));
            }
        }
    }
    __syncthreads();

#pragma unroll
    for (int mt = 0; mt < 2; mt++)
#pragma unroll
        for (int hf = 0; hf < 2; hf++) {
            int rr = mw * 32 + mt * 16 + hf * 8 + gid;
#pragma unroll
            for (int nt = 0; nt < 4; nt++) {
                int col = nw * 32 + nt * 8 + 2 * tig;
                *(float2*)&Cs[rr * 132 + col] =
                    make_float2(c[mt][nt][hf * 2 + 0], c[mt][nt][hf * 2 + 1]);
            }
        }
    __syncthreads();

    const int row = tid >> 2, q = tid & 3;
    float x[32];
    float ssum = 0.0f, ssq = 0.0f;
#pragma unroll
    for (int i = 0; i < 8; i++) {
        float4 v = *(float4*)&Cs[row * 132 + q * 32 + i * 4];
        float4 e = *(const float4*)&enc[(size_t)(m0 + row) * H_ + q * 32 + i * 4];
        x[4 * i + 0] = v.x + e.x; x[4 * i + 1] = v.y + e.y;
        x[4 * i + 2] = v.z + e.z; x[4 * i + 3] = v.w + e.w;
#pragma unroll
        for (int j = 0; j < 4; j++) {
            ssum += x[4 * i + j];
            ssq  += x[4 * i + j] * x[4 * i + j];
        }
    }
    ssum += __shfl_xor_sync(0xffffffffu, ssum, 1);
    ssum += __shfl_xor_sync(0xffffffffu, ssum, 2);
    ssq  += __shfl_xor_sync(0xffffffffu, ssq,  1);
    ssq  += __shfl_xor_sync(0xffffffffu, ssq,  2);
    float mean = ssum * (1.0f / 128.0f);
    float var  = ssq * (1.0f / 128.0f) - mean * mean;
    float rstd = rsqrtf(var + 1e-6f);

#pragma unroll
    for (int i = 0; i < 8; i++) {
        float4 g  = *(const float4*)&gamma[q * 32 + i * 4];
        float4 be = *(const float4*)&beta[q * 32 + i * 4];
        float4 y = make_float4((x[4 * i + 0] - mean) * rstd * g.x + be.x,
                               (x[4 * i + 1] - mean) * rstd * g.y + be.y,
                               (x[4 * i + 2] - mean) * rstd * g.z + be.z,
                               (x[4 * i + 3] - mean) * rstd * g.w + be.w);
        *(float4*)&out[(size_t)(m0 + row) * H_ + q * 32 + i * 4] = y;
    }
}

// =============================================================================
extern "C" void kernel_launch(void* const* d_in, const int* in_sizes, int n_in,
                              void* d_out, int out_size)
{
    const float* enc   = (const float*)d_in[0];
    const int*   mask  = (const int*)  d_in[1];
    const float* Wq    = (const float*)d_in[2];
    const float* Wk    = (const float*)d_in[3];
    const float* Wv    = (const float*)d_in[4];
    const float* Wo    = (const float*)d_in[5];
    const float* gamma = (const float*)d_in[6];
    const float* beta  = (const float*)d_in[7];
    float* out = (float*)d_out;

    prep_kernel<<<256, 256>>>(Wq, Wk, Wv, Wo);

    const int smem1 = 109056;
    cudaFuncSetAttribute(qkv_kernel, cudaFuncAttributeMaxDynamicSharedMemorySize, smem1);
    qkv_kernel<<<(B_ * S_) / 64, 256, smem1>>>(enc);

    const int smem2 = 184320;
    cudaFuncSetAttribute(attn_kernel, cudaFuncAttributeMaxDynamicSharedMemorySize, smem2);
    dim3 g2(S_ / 128, NH_, B_);
    attn_kernel<<<g2, 256, smem2>>>(mask);

    const int smem3 = 110592;
    cudaFuncSetAttribute(out_kernel, cudaFuncAttributeMaxDynamicSharedMemorySize, smem3);
    out_kernel<<<(B_ * S_) / 64, 256, smem3>>>(enc, gamma, beta, out);
}

// round 11
// speedup vs baseline: 2.4924x; 1.0115x over previous
#include <cuda_runtime.h>
#include <cuda_fp16.h>

#define B_    64
#define S_    512
#define H_    128
#define NH_   4
#define NHH_  512
#define QSCALE 0.08838834764831845f   /* 1/sqrt(128) */
#define NEG_INF_ -1e9f

// ---------------- packed fp16 scratch ----------------------------------------
// "Unit" = float2 (8B) = 2 half2: unit u holds (h2[j], h2[j+4]) with
// j = 8*(u>>2) + (u&3).  h2[j] = (T[2j], T[2j+1]) along the MMA k-dim.
__device__ float2 g_Qh [(size_t)B_ * NH_ * S_ * 32];      // [bh][s][32u]  (k=d 128)
__device__ float2 g_Kh [(size_t)B_ * NH_ * S_ * 32];      // [bh][s][32u]
__device__ float2 g_Vth[(size_t)B_ * NH_ * H_ * 4 * 32];  // [bh][d][kt4][32u] (128 kv/tile)
__device__ float2 g_ctxh[(size_t)B_ * S_ * 4 * 32];       // [tok][kc4][32u]
__device__ float2 g_Wh [3 * 512 * 32];                    // [mat][n][32u], Wq*QSCALE folded
__device__ float2 g_Woh[128 * 4 * 32];                    // [n][kc4][32u]

// ---------------- helpers ----------------------------------------------------
__device__ __forceinline__ unsigned h2u(float x, float y) {
    __half2 h = __floats2half2_rn(x, y);
    return *reinterpret_cast<unsigned*>(&h);
}
__device__ __forceinline__ unsigned hh2u(__half x, __half y) {
    __half2 h = __halves2half2(x, y);
    return *reinterpret_cast<unsigned*>(&h);
}
__device__ __forceinline__ unsigned fu(float x) { return __float_as_uint(x); }
__device__ __forceinline__ float    uf(unsigned u) { return __uint_as_float(u); }

__device__ __forceinline__ void mma_f16(float c[4],
                                        unsigned a0, unsigned a1, unsigned a2, unsigned a3,
                                        unsigned b0, unsigned b1) {
    asm volatile(
        "mma.sync.aligned.m16n8k16.row.col.f32.f16.f16.f32 "
        "{%0,%1,%2,%3}, {%4,%5,%6,%7}, {%8,%9}, {%0,%1,%2,%3};"
        : "+f"(c[0]), "+f"(c[1]), "+f"(c[2]), "+f"(c[3])
        : "r"(a0), "r"(a1), "r"(a2), "r"(a3), "r"(b0), "r"(b1));
}

__device__ __forceinline__ void cpa16(void* dst, const void* src) {
    unsigned d = (unsigned)__cvta_generic_to_shared(dst);
    asm volatile("cp.async.cg.shared.global [%0], [%1], 16;" :: "r"(d), "l"(src));
}
__device__ __forceinline__ void cp_commit() { asm volatile("cp.async.commit_group;"); }
template<int N> __device__ __forceinline__ void cp_wait() {
    asm volatile("cp.async.wait_group %0;" :: "n"(N));
}

// =============================================================================
// Kernel 0: pack weights to fp16 packed-unit layout. 65536 threads.
// =============================================================================
__global__ void __launch_bounds__(256) prep_kernel(
    const float* __restrict__ Wq, const float* __restrict__ Wk,
    const float* __restrict__ Wv, const float* __restrict__ Wo)
{
    int idx = blockIdx.x * 256 + threadIdx.x;
    if (idx < 3 * 512 * 32) {
        int u = idx & 31, n = (idx >> 5) & 511, mat = idx >> 14;
        const float* W = (mat == 0) ? Wq : (mat == 1) ? Wk : Wv;
        float scl = (mat == 0) ? QSCALE : 1.0f;
        int j = 8 * (u >> 2) + (u & 3);
        float2 v;
        v.x = uf(h2u(W[(size_t)(2 * j)     * NHH_ + n] * scl,
                     W[(size_t)(2 * j + 1) * NHH_ + n] * scl));
        v.y = uf(h2u(W[(size_t)(2 * j + 8) * NHH_ + n] * scl,
                     W[(size_t)(2 * j + 9) * NHH_ + n] * scl));
        g_Wh[idx] = v;
    } else {
        int i2 = idx - 3 * 512 * 32;
        int u = i2 & 31, kc = (i2 >> 5) & 3, n = i2 >> 7;
        int j = 8 * (u >> 2) + (u & 3);
        int kb = kc * 128;
        float2 v;
        v.x = uf(h2u(Wo[(size_t)(kb + 2 * j)     * H_ + n],
                     Wo[(size_t)(kb + 2 * j + 1) * H_ + n]));
        v.y = uf(h2u(Wo[(size_t)(kb + 2 * j + 8) * H_ + n],
                     Wo[(size_t)(kb + 2 * j + 9) * H_ + n]));
        g_Woh[(size_t)(n * 4 + kc) * 32 + u] = v;
    }
}

// =============================================================================
// Kernel 1: QKV projection (unchanged from R9 — verified).
// =============================================================================
__global__ void __launch_bounds__(256, 2) qkv_kernel(const float* __restrict__ enc)
{
    extern __shared__ float sm[];
    float2* Ap  = (float2*)sm;              // [0,4608)
    float2* Ws0 = (float2*)(sm + 4608);     // [4608,13824)
    float2* Ws1 = (float2*)(sm + 13824);    // [13824,23040)
    __half* Vst = (__half*)(sm + 23040);    // 64x132 halfs (16896 B)

    const int tid = threadIdx.x, lane = tid & 31, wid = tid >> 5;
    const int gid = lane >> 2, tig = lane & 3;
    const int mw = wid & 1, nw = wid >> 1;
    const int m0 = blockIdx.x * 64;
    const int r0 = mw * 32 + gid;
    __half2* Aph2 = (__half2*)Ap;

#pragma unroll
    for (int t = 0; t < 8; t++) {
        int idx = tid + t * 256;
        int r = idx >> 5, sl = idx & 31;
        float4 a = *(const float4*)&enc[(size_t)(m0 + r) * H_ + sl * 4];
        int j0 = 2 * sl, j1 = 2 * sl + 1;
        int u0 = 4 * (j0 >> 3) + (j0 & 3), c0 = (j0 >> 2) & 1;
        int u1 = 4 * (j1 >> 3) + (j1 & 3), c1 = (j1 >> 2) & 1;
        Aph2[(r * 36 + u0) * 2 + c0] = __floats2half2_rn(a.x, a.y);
        Aph2[(r * 36 + u1) * 2 + c1] = __floats2half2_rn(a.z, a.w);
    }

#pragma unroll
    for (int t = 0; t < 8; t++) {
        int idx = tid + t * 256;
        int r = idx >> 4, q = idx & 15;
        cpa16(&Ws0[r * 36 + 2 * q], &g_Wh[(size_t)(r << 5) + 2 * q]);
    }
    cp_commit();

    for (int ch = 0; ch < 12; ch++) {
        const int mat = ch >> 2, hq = ch & 3;
        float2* Wb = (ch & 1) ? Ws1 : Ws0;
        float2* Wn = (ch & 1) ? Ws0 : Ws1;

        __syncthreads();
        if (ch < 11) {
            const int nm = (ch + 1) >> 2, nh = (ch + 1) & 3;
#pragma unroll
            for (int t = 0; t < 8; t++) {
                int idx = tid + t * 256;
                int r = idx >> 4, q = idx & 15;
                cpa16(&Wn[r * 36 + 2 * q],
                      &g_Wh[(size_t)((nm * 512 + nh * 128 + r) << 5) + 2 * q]);
            }
            cp_commit();
            cp_wait<1>();
        } else {
            cp_wait<0>();
        }
        __syncthreads();

        float c[2][4][4];
#pragma unroll
        for (int mt = 0; mt < 2; mt++)
#pragma unroll
            for (int nt = 0; nt < 4; nt++)
#pragma unroll
                for (int j = 0; j < 4; j++) c[mt][nt][j] = 0.0f;

#pragma unroll
        for (int s2 = 0; s2 < 8; s2++) {
            float2 A0  = Ap[(r0)      * 36 + 4 * s2 + tig];
            float2 A8  = Ap[(r0 + 8)  * 36 + 4 * s2 + tig];
            float2 A16 = Ap[(r0 + 16) * 36 + 4 * s2 + tig];
            float2 A24 = Ap[(r0 + 24) * 36 + 4 * s2 + tig];
#pragma unroll
            for (int nt = 0; nt < 4; nt++) {
                float2 Bv = Wb[(nw * 32 + nt * 8 + gid) * 36 + 4 * s2 + tig];
                mma_f16(c[0][nt], fu(A0.x),  fu(A8.x),  fu(A0.y),  fu(A8.y),  fu(Bv.x), fu(Bv.y));
                mma_f16(c[1][nt], fu(A16.x), fu(A24.x), fu(A16.y), fu(A24.y), fu(Bv.x), fu(Bv.y));
            }
        }

        if (mat < 2) {
            float2* dst = (mat == 0) ? g_Qh : g_Kh;
#pragma unroll
            for (int mt = 0; mt < 2; mt++)
#pragma unroll
                for (int hf = 0; hf < 2; hf++) {
                    int rr = mw * 32 + mt * 16 + hf * 8 + gid;
                    int tok = m0 + rr, bbv = tok >> 9, srow = tok & 511;
                    size_t base = ((size_t)(bbv * NH_ + hq) * S_ + srow) * 32;
#pragma unroll
                    for (int p = 0; p < 2; p++) {
                        float2 v;
                        v.x = uf(h2u(c[mt][2 * p][hf * 2],     c[mt][2 * p][hf * 2 + 1]));
                        v.y = uf(h2u(c[mt][2 * p + 1][hf * 2], c[mt][2 * p + 1][hf * 2 + 1]));
                        dst[base + 8 * nw + 4 * p + tig] = v;
                    }
                }
        } else {
            __syncthreads();
#pragma unroll
            for (int mt = 0; mt < 2; mt++)
#pragma unroll
                for (int hf = 0; hf < 2; hf++) {
                    int rr = mw * 32 + mt * 16 + hf * 8 + gid;
#pragma unroll
                    for (int nt = 0; nt < 4; nt++) {
                        int jd = 16 * nw + 4 * nt + tig;
                        *(__half2*)&Vst[rr * 132 + 2 * jd] =
                            __floats2half2_rn(c[mt][nt][hf * 2], c[mt][nt][hf * 2 + 1]);
                    }
                }
            __syncthreads();
            const int bbv = m0 >> 9;
            const int kt4 = (m0 & 511) >> 7;
            const int hi  = (m0 >> 6) & 1;
            size_t vbase = (size_t)(bbv * NH_ + hq) * H_;
#pragma unroll
            for (int t = 0; t < 8; t++) {
                int idx = tid + t * 256;
                int d = idx >> 4, ul = idx & 15;
                int j0l = 8 * (ul >> 2) + (ul & 3);
                float2 o;
                o.x = uf(hh2u(Vst[(2 * j0l)     * 132 + d], Vst[(2 * j0l + 1) * 132 + d]));
                o.y = uf(hh2u(Vst[(2 * j0l + 8) * 132 + d], Vst[(2 * j0l + 9) * 132 + d]));
                g_Vth[((vbase + d) * 4 + kt4) * 32 + 16 * hi + ul] = o;
            }
        }
    }
}

// =============================================================================
// Kernel 2: FA2 flash attention, K-TILE 64, 2 CTAs/SM.
// Q-tile 128, 8 warps; each warp owns 16 q-rows x full 64-k width.
// Softmax warp-local, P in registers.  8 kt iters, double-buffered K/V.
// smem 114688 B: Qh 128x36u, Kb0/1 64x36u, Vb0/1 128x20u.
// =============================================================================
__global__ void __launch_bounds__(256, 2) attn_kernel(const int* __restrict__ mask)
{
    extern __shared__ float sm[];
    float2* Qh  = (float2*)sm;               // 128x36u  floats [0,9216)
    float2* Kb0 = (float2*)(sm + 9216);      // 64x36u   [9216,13824)
    float2* Kb1 = (float2*)(sm + 13824);     // [13824,18432)
    float2* Vb0 = (float2*)(sm + 18432);     // 128x20u  [18432,23552)
    float2* Vb1 = (float2*)(sm + 23552);     // [23552,28672)

    const int tid = threadIdx.x, lane = tid & 31, wq = tid >> 5;
    const int gid = lane >> 2, tig = lane & 3;
    const int q0 = blockIdx.x * 128;
    const int hq = blockIdx.y, bb = blockIdx.z;
    const int bh = bb * NH_ + hq;
    const int r0 = wq * 16 + gid;
    const int gq0 = q0 + r0, gq1 = gq0 + 8;

    // prefetch Q (128x32u) + K tile 0 (64x32u) + V tile 0 (128x16u)
#pragma unroll
    for (int t = 0; t < 8; t++) {
        int idx = tid + t * 256;
        int r = idx >> 4, q = idx & 15;
        cpa16(&Qh[r * 36 + 2 * q], &g_Qh[((size_t)bh * S_ + q0 + r) * 32 + 2 * q]);
    }
#pragma unroll
    for (int t = 0; t < 4; t++) {
        int idx = tid + t * 256;
        int r = idx >> 4, q = idx & 15;
        cpa16(&Kb0[r * 36 + 2 * q], &g_Kh[((size_t)bh * S_ + r) * 32 + 2 * q]);
    }
#pragma unroll
    for (int t = 0; t < 4; t++) {
        int idx = tid + t * 256;
        int d = idx >> 3, q = idx & 7;
        cpa16(&Vb0[d * 20 + 2 * q], &g_Vth[(((size_t)bh * H_ + d) * 4) * 32 + 2 * q]);
    }
    cp_commit();

    float O[16][4];
#pragma unroll
    for (int nt = 0; nt < 16; nt++)
#pragma unroll
        for (int j = 0; j < 4; j++) O[nt][j] = 0.0f;
    float m0v = -1e30f, m1v = -1e30f, l0 = 0.0f, l1 = 0.0f;

    for (int kt = 0; kt < 8; kt++) {
        float2* Kc = (kt & 1) ? Kb1 : Kb0;
        float2* Vc = (kt & 1) ? Vb1 : Vb0;
        float2* Kn = (kt & 1) ? Kb0 : Kb1;
        float2* Vn = (kt & 1) ? Vb0 : Vb1;
        const int k0 = kt * 64;

        __syncthreads();                     // all warps done reading Kn/Vn
        if (kt < 7) {
            const int kn0 = k0 + 64;
#pragma unroll
            for (int t = 0; t < 4; t++) {
                int idx = tid + t * 256;
                int r = idx >> 4, q = idx & 15;
                cpa16(&Kn[r * 36 + 2 * q],
                      &g_Kh[((size_t)bh * S_ + kn0 + r) * 32 + 2 * q]);
            }
#pragma unroll
            for (int t = 0; t < 4; t++) {
                int idx = tid + t * 256;
                int d = idx >> 3, q = idx & 7;
                cpa16(&Vn[d * 20 + 2 * q],
                      &g_Vth[(((size_t)bh * H_ + d) * 4 + ((kt + 1) >> 1)) * 32
                             + 16 * ((kt + 1) & 1) + 2 * q]);
            }
            cp_commit();
            cp_wait<1>();                    // tile kt complete
        } else {
            cp_wait<0>();
        }
        __syncthreads();                     // tile kt visible

        // ---- S = Q K^T : 16 q-rows x 64 k-cols per warp ----
        float c[8][4];
#pragma unroll
        for (int nt = 0; nt < 8; nt++)
#pragma unroll
            for (int j = 0; j < 4; j++) c[nt][j] = 0.0f;
#pragma unroll
        for (int s2 = 0; s2 < 8; s2++) {
            float2 A0 = Qh[(r0)     * 36 + 4 * s2 + tig];
            float2 A8 = Qh[(r0 + 8) * 36 + 4 * s2 + tig];
#pragma unroll
            for (int nt = 0; nt < 8; nt++) {
                float2 Bv = Kc[(8 * nt + gid) * 36 + 4 * s2 + tig];
                mma_f16(c[nt], fu(A0.x), fu(A8.x), fu(A0.y), fu(A8.y), fu(Bv.x), fu(Bv.y));
            }
        }

        // ---- mask + row max (warp-local) ----
        float mx0 = -1e30f, mx1 = -1e30f;
#pragma unroll
        for (int nt = 0; nt < 8; nt++) {
            int kc = k0 + 8 * nt + 2 * tig;
            int2 mk0 = *(const int2*)&mask[((size_t)bb * S_ + gq0) * S_ + kc];
            int2 mk1 = *(const int2*)&mask[((size_t)bb * S_ + gq1) * S_ + kc];
            if (mk0.x == 0) c[nt][0] = NEG_INF_;
            if (mk0.y == 0) c[nt][1] = NEG_INF_;
            if (mk1.x == 0) c[nt][2] = NEG_INF_;
            if (mk1.y == 0) c[nt][3] = NEG_INF_;
            mx0 = fmaxf(mx0, fmaxf(c[nt][0], c[nt][1]));
            mx1 = fmaxf(mx1, fmaxf(c[nt][2], c[nt][3]));
        }
        mx0 = fmaxf(mx0, __shfl_xor_sync(0xffffffffu, mx0, 1));
        mx0 = fmaxf(mx0, __shfl_xor_sync(0xffffffffu, mx0, 2));
        mx1 = fmaxf(mx1, __shfl_xor_sync(0xffffffffu, mx1, 1));
        mx1 = fmaxf(mx1, __shfl_xor_sync(0xffffffffu, mx1, 2));

        float nm0 = fmaxf(m0v, mx0), nm1 = fmaxf(m1v, mx1);
        float al0 = __expf(m0v - nm0), al1 = __expf(m1v - nm1);
        m0v = nm0; m1v = nm1;

        float s0 = 0.0f, s1 = 0.0f;
#pragma unroll
        for (int nt = 0; nt < 8; nt++) {
            c[nt][0] = __expf(c[nt][0] - nm0);
            c[nt][1] = __expf(c[nt][1] - nm0);
            c[nt][2] = __expf(c[nt][2] - nm1);
            c[nt][3] = __expf(c[nt][3] - nm1);
            s0 += c[nt][0] + c[nt][1];
            s1 += c[nt][2] + c[nt][3];
        }
        s0 += __shfl_xor_sync(0xffffffffu, s0, 1);
        s0 += __shfl_xor_sync(0xffffffffu, s0, 2);
        s1 += __shfl_xor_sync(0xffffffffu, s1, 1);
        s1 += __shfl_xor_sync(0xffffffffu, s1, 2);
        l0 = l0 * al0 + s0;
        l1 = l1 * al1 + s1;

#pragma unroll
        for (int nt = 0; nt < 16; nt++) {
            O[nt][0] *= al0; O[nt][1] *= al0;
            O[nt][2] *= al1; O[nt][3] *= al1;
        }

        // ---- O += P @ V : P from c-frags (c[2p],c[2p+1] = a-frag of k-step p) ----
#pragma unroll
        for (int p = 0; p < 4; p++) {
            unsigned pa0 = h2u(c[2 * p][0],     c[2 * p][1]);
            unsigned pa1 = h2u(c[2 * p][2],     c[2 * p][3]);
            unsigned pa2 = h2u(c[2 * p + 1][0], c[2 * p + 1][1]);
            unsigned pa3 = h2u(c[2 * p + 1][2], c[2 * p + 1][3]);
#pragma unroll
            for (int ntd = 0; ntd < 16; ntd++) {
                float2 Bv = Vc[(8 * ntd + gid) * 20 + 4 * p + tig];
                mma_f16(O[ntd], pa0, pa1, pa2, pa3, fu(Bv.x), fu(Bv.y));
            }
        }
    }

    // ---- normalize, pack ctx units ----
    float inv0 = 1.0f / l0, inv1 = 1.0f / l1;
    size_t cb0 = ((size_t)(bb * S_ + gq0) * 4 + hq) * 32;
    size_t cb1 = ((size_t)(bb * S_ + gq1) * 4 + hq) * 32;
#pragma unroll
    for (int p = 0; p < 8; p++) {
        float2 v0, v1;
        v0.x = uf(h2u(O[2 * p][0] * inv0,     O[2 * p][1] * inv0));
        v0.y = uf(h2u(O[2 * p + 1][0] * inv0, O[2 * p + 1][1] * inv0));
        v1.x = uf(h2u(O[2 * p][2] * inv1,     O[2 * p][3] * inv1));
        v1.y = uf(h2u(O[2 * p + 1][2] * inv1, O[2 * p + 1][3] * inv1));
        g_ctxh[cb0 + 4 * p + tig] = v0;
        g_ctxh[cb1 + 4 * p + tig] = v1;
    }
}

// =============================================================================
// Kernel 3: out = ctx @ Wo + enc, LayerNorm.  (unchanged from R9)
// =============================================================================
__global__ void __launch_bounds__(256, 2) out_kernel(
    const float* __restrict__ enc, const float* __restrict__ gamma,
    const float* __restrict__ beta, float* __restrict__ out)
{
    extern __shared__ float sm[];
    float2* Ap0 = (float2*)sm;
    float2* Ap1 = (float2*)(sm + 4608);
    float2* Ws0 = (float2*)(sm + 9216);
    float2* Ws1 = (float2*)(sm + 18432);
    float*  Cs  = sm;

    const int tid = threadIdx.x, lane = tid & 31, wid = tid >> 5;
    const int gid = lane >> 2, tig = lane & 3;
    const int mw = wid & 1, nw = wid >> 1;
    const int m0 = blockIdx.x * 64;
    const int r0 = mw * 32 + gid;

#pragma unroll
    for (int t = 0; t < 4; t++) {
        int idx = tid + t * 256;
        int r = idx >> 4, q = idx & 15;
        cpa16(&Ap0[r * 36 + 2 * q], &g_ctxh[((size_t)(m0 + r) * 4) * 32 + 2 * q]);
    }
#pragma unroll
    for (int t = 0; t < 8; t++) {
        int idx = tid + t * 256;
        int r = idx >> 4, q = idx & 15;
        cpa16(&Ws0[r * 36 + 2 * q], &g_Woh[((size_t)r * 4) * 32 + 2 * q]);
    }
    cp_commit();

    float c[2][4][4];
#pragma unroll
    for (int mt = 0; mt < 2; mt++)
#pragma unroll
        for (int nt = 0; nt < 4; nt++)
#pragma unroll
            for (int j = 0; j < 4; j++) c[mt][nt][j] = 0.0f;

    for (int kc = 0; kc < 4; kc++) {
        float2* Ab = (kc & 1) ? Ap1 : Ap0;
        float2* Wb = (kc & 1) ? Ws1 : Ws0;
        float2* An = (kc & 1) ? Ap0 : Ap1;
        float2* Wn = (kc & 1) ? Ws0 : Ws1;

        __syncthreads();
        if (kc < 3) {
#pragma unroll
            for (int t = 0; t < 4; t++) {
                int idx = tid + t * 256;
                int r = idx >> 4, q = idx & 15;
                cpa16(&An[r * 36 + 2 * q],
                      &g_ctxh[((size_t)(m0 + r) * 4 + kc + 1) * 32 + 2 * q]);
            }
#pragma unroll
            for (int t = 0; t < 8; t++) {
                int idx = tid + t * 256;
                int r = idx >> 4, q = idx & 15;
                cpa16(&Wn[r * 36 + 2 * q],
                      &g_Woh[((size_t)r * 4 + kc + 1) * 32 + 2 * q]);
            }
            cp_commit();
            cp_wait<1>();
        } else {
            cp_wait<0>();
        }
        __syncthreads();

#pragma unroll
        for (int s2 = 0; s2 < 8; s2++) {
            float2 A0  = Ab[(r0)      * 36 + 4 * s2 + tig];
            float2 A8  = Ab[(r0 + 8)  * 36 + 4 * s2 + tig];
            float2 A16 = Ab[(r0 + 16) * 36 + 4 * s2 + tig];
            float2 A24 = Ab[(r0 + 24) * 36 + 4 * s2 + tig];
#pragma unroll
            for (int nt = 0; nt < 4; nt++) {
                float2 Bv = Wb[(nw * 32 + nt * 8 + gid) * 36 + 4 * s2 + tig];
                mma_f16(c[0][nt], fu(A0.x),  fu(A8.x),  fu(A0.y),  fu(A8.y),  fu(Bv.x), fu(Bv.y));
                mma_f16(c[1][nt], fu(A16.x), fu(A24.x), fu(A16.y), fu(A24.y), fu(Bv.x), fu(Bv.y));
            }
        }
    }
    __syncthreads();

#pragma unroll
    for (int mt = 0; mt < 2; mt++)
#pragma unroll
        for (int hf = 0; hf < 2; hf++) {
            int rr = mw * 32 + mt * 16 + hf * 8 + gid;
#pragma unroll
            for (int nt = 0; nt < 4; nt++) {
                int col = nw * 32 + nt * 8 + 2 * tig;
                *(float2*)&Cs[rr * 132 + col] =
                    make_float2(c[mt][nt][hf * 2 + 0], c[mt][nt][hf * 2 + 1]);
            }
        }
    __syncthreads();

    const int row = tid >> 2, q = tid & 3;
    float x[32];
    float ssum = 0.0f, ssq = 0.0f;
#pragma unroll
    for (int i = 0; i < 8; i++) {
        float4 v = *(float4*)&Cs[row * 132 + q * 32 + i * 4];
        float4 e = *(const float4*)&enc[(size_t)(m0 + row) * H_ + q * 32 + i * 4];
        x[4 * i + 0] = v.x + e.x; x[4 * i + 1] = v.y + e.y;
        x[4 * i + 2] = v.z + e.z; x[4 * i + 3] = v.w + e.w;
#pragma unroll
        for (int j = 0; j < 4; j++) {
            ssum += x[4 * i + j];
            ssq  += x[4 * i + j] * x[4 * i + j];
        }
    }
    ssum += __shfl_xor_sync(0xffffffffu, ssum, 1);
    ssum += __shfl_xor_sync(0xffffffffu, ssum, 2);
    ssq  += __shfl_xor_sync(0xffffffffu, ssq,  1);
    ssq  += __shfl_xor_sync(0xffffffffu, ssq,  2);
    float mean = ssum * (1.0f / 128.0f);
    float var  = ssq * (1.0f / 128.0f) - mean * mean;
    float rstd = rsqrtf(var + 1e-6f);

#pragma unroll
    for (int i = 0; i < 8; i++) {
        float4 g  = *(const float4*)&gamma[q * 32 + i * 4];
        float4 be = *(const float4*)&beta[q * 32 + i * 4];
        float4 y = make_float4((x[4 * i + 0] - mean) * rstd * g.x + be.x,
                               (x[4 * i + 1] - mean) * rstd * g.y + be.y,
                               (x[4 * i + 2] - mean) * rstd * g.z + be.z,
                               (x[4 * i + 3] - mean) * rstd * g.w + be.w);
        *(float4*)&out[(size_t)(m0 + row) * H_ + q * 32 + i * 4] = y;
    }
}

// =============================================================================
extern "C" void kernel_launch(void* const* d_in, const int* in_sizes, int n_in,
                              void* d_out, int out_size)
{
    const float* enc   = (const float*)d_in[0];
    const int*   mask  = (const int*)  d_in[1];
    const float* Wq    = (const float*)d_in[2];
    const float* Wk    = (const float*)d_in[3];
    const float* Wv    = (const float*)d_in[4];
    const float* Wo    = (const float*)d_in[5];
    const float* gamma = (const float*)d_in[6];
    const float* beta  = (const float*)d_in[7];
    float* out = (float*)d_out;

    prep_kernel<<<256, 256>>>(Wq, Wk, Wv, Wo);

    const int smem1 = 109056;
    cudaFuncSetAttribute(qkv_kernel, cudaFuncAttributeMaxDynamicSharedMemorySize, smem1);
    qkv_kernel<<<(B_ * S_) / 64, 256, smem1>>>(enc);

    const int smem2 = 114688;
    cudaFuncSetAttribute(attn_kernel, cudaFuncAttributeMaxDynamicSharedMemorySize, smem2);
    dim3 g2(S_ / 128, NH_, B_);
    attn_kernel<<<g2, 256, smem2>>>(mask);

    const int smem3 = 110592;
    cudaFuncSetAttribute(out_kernel, cudaFuncAttributeMaxDynamicSharedMemorySize, smem3);
    out_kernel<<<(B_ * S_) / 64, 256, smem3>>>(enc, gamma, beta, out);
}